// round 1
// baseline (speedup 1.0000x reference)
#include <cuda_runtime.h>
#include <math.h>

#define BATCH   2
#define SEQ     4096
#define DMODEL  512
#define NH      8
#define HD      64
#define NC      128     // S / CB(32)
#define NS      64      // S / SB(64)
#define TOPK    16
#define NROWS   (BATCH*SEQ)   // 8192

// ---------------- scratch (device globals; no allocations) ----------------
__device__ float d_Q[NROWS*DMODEL];
__device__ float d_K[NROWS*DMODEL];
__device__ float d_V[NROWS*DMODEL];
__device__ float d_O[NROWS*DMODEL];
__device__ float d_KC[BATCH*NH*NC*HD];
__device__ float d_VC[BATCH*NH*NC*HD];
__device__ float d_G[NROWS*3];
__device__ int   d_SEL[BATCH*NH*NS*TOPK];

// ---------------- generic 512-K / 512-N fp32 GEMM -------------------------
// mode 0/1/2 : C = x @ {Wq,Wk,Wv} -> d_Q/d_K/d_V
// mode 3     : C = d_O @ Wo       -> Cext (harness d_out)
__global__ __launch_bounds__(256) void gemm512(const float* __restrict__ Aext,
    const float* __restrict__ B0, const float* __restrict__ B1,
    const float* __restrict__ B2, float* __restrict__ Cext, int modeBase)
{
    int mode = modeBase + blockIdx.z;
    const float* A  = (mode == 3) ? d_O : Aext;
    const float* Bm = (mode == 1) ? B1 : (mode == 2) ? B2 : B0;
    float* C = (mode == 0) ? d_Q : (mode == 1) ? d_K : (mode == 2) ? d_V : Cext;

    __shared__ float As[16][68];
    __shared__ float Bs[16][68];
    int tid = threadIdx.x;
    int tx = tid & 15, ty = tid >> 4;
    int m0 = blockIdx.y * 64, n0 = blockIdx.x * 64;
    float acc[4][4];
#pragma unroll
    for (int i = 0; i < 4; i++)
#pragma unroll
        for (int j = 0; j < 4; j++) acc[i][j] = 0.f;

    int la_m = (tid * 4) >> 4, la_k = (tid * 4) & 15;
    int lb_k = (tid * 4) >> 6, lb_n = (tid * 4) & 63;

    for (int k0 = 0; k0 < 512; k0 += 16) {
        float4 av = *(const float4*)(A + (size_t)(m0 + la_m) * 512 + k0 + la_k);
        As[la_k + 0][la_m] = av.x; As[la_k + 1][la_m] = av.y;
        As[la_k + 2][la_m] = av.z; As[la_k + 3][la_m] = av.w;
        *(float4*)(&Bs[lb_k][lb_n]) =
            *(const float4*)(Bm + (size_t)(k0 + lb_k) * 512 + n0 + lb_n);
        __syncthreads();
#pragma unroll
        for (int kk = 0; kk < 16; kk++) {
            float4 a4 = *(const float4*)(&As[kk][ty * 4]);
            float4 b4 = *(const float4*)(&Bs[kk][tx * 4]);
            float ar[4] = {a4.x, a4.y, a4.z, a4.w};
            float br[4] = {b4.x, b4.y, b4.z, b4.w};
#pragma unroll
            for (int i = 0; i < 4; i++)
#pragma unroll
                for (int j = 0; j < 4; j++) acc[i][j] += ar[i] * br[j];
        }
        __syncthreads();
    }
#pragma unroll
    for (int i = 0; i < 4; i++) {
        float4 v = make_float4(acc[i][0], acc[i][1], acc[i][2], acc[i][3]);
        *(float4*)(C + (size_t)(m0 + ty * 4 + i) * 512 + n0 + tx * 4) = v;
    }
}

// ---------------- gate: sigmoid(x @ Wg), Wg is [512,3] --------------------
__global__ __launch_bounds__(128) void gate_kernel(const float* __restrict__ x,
                                                   const float* __restrict__ Wg)
{
    int row = blockIdx.x;
    int tid = threadIdx.x, lane = tid & 31, w = tid >> 5;
    float p0 = 0, p1 = 0, p2 = 0;
    for (int d = tid; d < 512; d += 128) {
        float xv = x[(size_t)row * 512 + d];
        p0 += xv * Wg[d * 3 + 0];
        p1 += xv * Wg[d * 3 + 1];
        p2 += xv * Wg[d * 3 + 2];
    }
#pragma unroll
    for (int o = 16; o; o >>= 1) {
        p0 += __shfl_xor_sync(0xffffffffu, p0, o);
        p1 += __shfl_xor_sync(0xffffffffu, p1, o);
        p2 += __shfl_xor_sync(0xffffffffu, p2, o);
    }
    __shared__ float red[3][4];
    if (lane == 0) { red[0][w] = p0; red[1][w] = p1; red[2][w] = p2; }
    __syncthreads();
    if (tid < 3) {
        float v = red[tid][0] + red[tid][1] + red[tid][2] + red[tid][3];
        d_G[row * 3 + tid] = 1.f / (1.f + expf(-v));
    }
}

// ---------------- compressed K/V: mean over CB=32 rows ---------------------
__global__ __launch_bounds__(256) void compress_kernel()
{
    int idx = blockIdx.x * 256 + threadIdx.x;      // 2^17 threads
    int d = idx & 63, n = (idx >> 6) & 127, h = (idx >> 13) & 7, b = idx >> 16;
    const float* kp = d_K + (size_t)(b * SEQ + n * 32) * 512 + h * 64 + d;
    const float* vp = d_V + (size_t)(b * SEQ + n * 32) * 512 + h * 64 + d;
    float ks = 0, vs = 0;
#pragma unroll
    for (int r = 0; r < 32; r++) { ks += kp[r * 512]; vs += vp[r * 512]; }
    d_KC[idx] = ks * (1.f / 32.f);
    d_VC[idx] = vs * (1.f / 32.f);
}

// ---------------- compressed attention + importance + top-k ----------------
// one block per (b, h, query-block g of 64): writes d_O = g0*out_c, d_SEL
__global__ __launch_bounds__(256) void cmp_attn_kernel()
{
    extern __shared__ float sm[];
    float* kc   = sm;                 // 128*65
    float* vc   = kc  + 128 * 65;     // 128*65
    float* qs   = vc  + 128 * 65;     // 64*65
    float* pcs  = qs  + 64 * 65;      // 8*128 (per-warp probs)
    float* imps = pcs + 8 * 128;      // 64*65 (per-query block importance)
    float* impb = imps + 64 * 65;     // 64

    int g = blockIdx.x, h = blockIdx.y, b = blockIdx.z;
    int tid = threadIdx.x, lane = tid & 31, w = tid >> 5;

    int cbase = ((b * NH + h) * NC) * HD;
    for (int i = tid; i < NC * HD; i += 256) {
        int n = i >> 6, d = i & 63;
        kc[n * 65 + d] = d_KC[cbase + i];
        vc[n * 65 + d] = d_VC[cbase + i];
    }
    for (int i = tid; i < 64 * 64; i += 256) {
        int r = i >> 6, d = i & 63;
        qs[r * 65 + d] = d_Q[(size_t)(b * SEQ + g * 64 + r) * 512 + h * 64 + d];
    }
    __syncthreads();

    for (int itq = 0; itq < 8; itq++) {
        int qr = w * 8 + itq;
        int pos = g * 64 + qr;
        int nvalid = (pos >= 31) ? ((pos - 31) >> 5) + 1 : 0;
        float s[4];
#pragma unroll
        for (int kk = 0; kk < 4; kk++) {
            int c = lane + 32 * kk;
            if (c < nvalid) {
                float a = 0;
#pragma unroll
                for (int d = 0; d < 64; d++) a += qs[qr * 65 + d] * kc[c * 65 + d];
                s[kk] = a * 0.125f;
            } else s[kk] = -1e30f;
        }
        float mx = fmaxf(fmaxf(s[0], s[1]), fmaxf(s[2], s[3]));
#pragma unroll
        for (int o = 16; o; o >>= 1) mx = fmaxf(mx, __shfl_xor_sync(0xffffffffu, mx, o));
        float e[4], ls = 0;
#pragma unroll
        for (int kk = 0; kk < 4; kk++) {
            e[kk] = (nvalid > 0) ? __expf(s[kk] - mx) : 0.f;
            ls += e[kk];
        }
#pragma unroll
        for (int o = 16; o; o >>= 1) ls += __shfl_xor_sync(0xffffffffu, ls, o);
        float inv = (nvalid > 0) ? 1.f / ls : 0.f;
#pragma unroll
        for (int kk = 0; kk < 4; kk++) pcs[w * 128 + lane + 32 * kk] = e[kk] * inv;
        __syncwarp();
        // importance per selection block (r=2 chunks per block)
#pragma unroll
        for (int jj = 0; jj < 2; jj++) {
            int j = lane + 32 * jj;
            imps[qr * 65 + j] = pcs[w * 128 + 2 * j] + pcs[w * 128 + 2 * j + 1];
        }
        // out_c (each lane: dims lane, lane+32)
        float o0 = 0, o1 = 0;
        for (int c = 0; c < 128; c++) {
            float p = pcs[w * 128 + c];
            o0 += p * vc[c * 65 + lane];
            o1 += p * vc[c * 65 + lane + 32];
        }
        float g0 = d_G[(b * SEQ + pos) * 3 + 0];
        size_t ob = (size_t)(b * SEQ + pos) * 512 + h * 64;
        d_O[ob + lane]      = g0 * o0;
        d_O[ob + lane + 32] = g0 * o1;
        __syncwarp();
    }
    __syncthreads();
    // deterministic reduce importance over the 64 queries in this block
    if (tid < 64) {
        float v = 0;
        for (int q = 0; q < 64; q++) v += imps[q * 65 + tid];
        impb[tid] = v;
    }
    __syncthreads();
    // top-k (warp 0), tie-break to lowest index (matches jax.lax.top_k)
    if (w == 0) {
        int j0 = lane, j1 = lane + 32;
        float v0 = (j0 <= g) ? impb[j0] + (j0 == g ? 1e9f : 0.f) : -1e30f;
        float v1 = (j1 <= g) ? impb[j1] + (j1 == g ? 1e9f : 0.f) : -1e30f;
        int selbase = ((b * NH + h) * NS + g) * TOPK;
        for (int r = 0; r < TOPK; r++) {
            float bv; int bi;
            if (v0 >= v1) { bv = v0; bi = j0; } else { bv = v1; bi = j1; }
#pragma unroll
            for (int o = 16; o; o >>= 1) {
                float ov = __shfl_xor_sync(0xffffffffu, bv, o);
                int   oi = __shfl_xor_sync(0xffffffffu, bi, o);
                if (ov > bv || (ov == bv && oi < bi)) { bv = ov; bi = oi; }
            }
            if (lane == 0) d_SEL[selbase + r] = bi;
            if (bi == j0) v0 = -3e30f;
            if (bi == j1) v1 = -3e30f;
        }
    }
}

// ---------------- selection / window flash attention -----------------------
// mode 0: 16 selected 64-key blocks (mask key<=q)
// mode 1: 9 tiles g-8..g (mask q-512 < key <= q)
// d_O += gate * out
__global__ __launch_bounds__(256) void sel_win_kernel(int mode)
{
    extern __shared__ float sm[];
    float* qs = sm;               // 64*68
    float* Ks = qs + 64 * 68;     // 64*68
    float* Vs = Ks + 64 * 68;     // 64*68
    float* ps = Vs + 64 * 68;     // 64*64

    int g = blockIdx.x, h = blockIdx.y, b = blockIdx.z;
    int tid = threadIdx.x, lane = tid & 31, w = tid >> 5;
    int qi = w * 8 + (lane >> 2), sub = lane & 3;
    int qpos = g * 64 + qi;

    for (int i = tid; i < 4096; i += 256) {
        int r = i >> 6, d = i & 63;
        qs[r * 68 + d] = d_Q[(size_t)(b * SEQ + g * 64 + r) * 512 + h * 64 + d];
    }
    float acc[16];
#pragma unroll
    for (int dd = 0; dd < 16; dd++) acc[dd] = 0.f;
    float m = -1e30f, ssum = 0.f;
    int niter = mode ? 9 : TOPK;
    int selbase = ((b * NH + h) * NS + g) * TOPK;
    __syncthreads();

    for (int it = 0; it < niter; it++) {
        int kb = mode ? (g - 8 + it) : d_SEL[selbase + it];
        if (kb < 0) continue;                 // uniform across block
        __syncthreads();
        size_t kbase = (size_t)(b * SEQ + kb * 64) * 512 + h * 64;
        for (int i = tid; i < 4096; i += 256) {
            int r = i >> 6, d = i & 63;
            Ks[r * 68 + d] = d_K[kbase + (size_t)r * 512 + d];
            Vs[r * 68 + d] = d_V[kbase + (size_t)r * 512 + d];
        }
        __syncthreads();

        float sc[16];
        const float4* qv = (const float4*)(qs + qi * 68);
#pragma unroll
        for (int j = 0; j < 16; j++) {
            int kk = 4 * j + sub;
            int kp = kb * 64 + kk;
            bool valid = (kp <= qpos) && (!mode || (kp + 512 > qpos));
            if (valid) {
                const float4* kv = (const float4*)(Ks + kk * 68);
                float a = 0;
#pragma unroll
                for (int d4 = 0; d4 < 16; d4++) {
                    float4 q4 = qv[d4], k4 = kv[d4];
                    a += q4.x * k4.x + q4.y * k4.y + q4.z * k4.z + q4.w * k4.w;
                }
                sc[j] = a * 0.125f;
            } else sc[j] = -1e30f;
        }
        float mx = sc[0];
#pragma unroll
        for (int j = 1; j < 16; j++) mx = fmaxf(mx, sc[j]);
        mx = fmaxf(mx, __shfl_xor_sync(0xffffffffu, mx, 1));
        mx = fmaxf(mx, __shfl_xor_sync(0xffffffffu, mx, 2));
        float newm = fmaxf(m, mx);
        bool active = (newm > -1e29f);        // guards fully-masked first tiles
        float corr = active ? __expf(m - newm) : 1.f;
        ssum *= corr;
#pragma unroll
        for (int dd = 0; dd < 16; dd++) acc[dd] *= corr;
        float ls = 0;
#pragma unroll
        for (int j = 0; j < 16; j++) {
            float p = active ? __expf(sc[j] - newm) : 0.f;
            ls += p;
            ps[qi * 64 + 4 * j + sub] = p;
        }
        ls += __shfl_xor_sync(0xffffffffu, ls, 1);
        ls += __shfl_xor_sync(0xffffffffu, ls, 2);
        ssum += ls;
        if (active) m = newm;
        __syncwarp();
        for (int k = 0; k < 64; k++) {
            float pv = ps[qi * 64 + k];
            const float4* vr = (const float4*)(Vs + k * 68 + sub * 16);
#pragma unroll
            for (int t = 0; t < 4; t++) {
                float4 vv = vr[t];
                acc[4 * t + 0] += pv * vv.x;
                acc[4 * t + 1] += pv * vv.y;
                acc[4 * t + 2] += pv * vv.z;
                acc[4 * t + 3] += pv * vv.w;
            }
        }
        __syncwarp();
    }
    float inv = 1.f / ssum;                  // self key always valid -> ssum>0
    float gv = d_G[(b * SEQ + qpos) * 3 + (mode ? 2 : 1)];
    size_t ob = (size_t)(b * SEQ + qpos) * 512 + h * 64 + sub * 16;
#pragma unroll
    for (int t = 0; t < 4; t++) {
        float4 cur = *(float4*)(d_O + ob + 4 * t);
        cur.x += gv * acc[4 * t + 0] * inv;
        cur.y += gv * acc[4 * t + 1] * inv;
        cur.z += gv * acc[4 * t + 2] * inv;
        cur.w += gv * acc[4 * t + 3] * inv;
        *(float4*)(d_O + ob + 4 * t) = cur;
    }
}

// ---------------------------------------------------------------------------
extern "C" void kernel_launch(void* const* d_in, const int* in_sizes, int n_in,
                              void* d_out, int out_size)
{
    const float* x  = (const float*)d_in[0];
    const float* Wq = (const float*)d_in[1];
    const float* Wk = (const float*)d_in[2];
    const float* Wv = (const float*)d_in[3];
    const float* Wo = (const float*)d_in[4];
    const float* Wg = (const float*)d_in[5];
    float* y = (float*)d_out;

    cudaFuncSetAttribute(cmp_attn_kernel,
                         cudaFuncAttributeMaxDynamicSharedMemorySize, 104192);
    cudaFuncSetAttribute(sel_win_kernel,
                         cudaFuncAttributeMaxDynamicSharedMemorySize, 68608);

    // Q, K, V projections
    gemm512<<<dim3(8, 128, 3), 256>>>(x, Wq, Wk, Wv, nullptr, 0);
    // gates
    gate_kernel<<<NROWS, 128>>>(x, Wg);
    // compressed K/V means
    compress_kernel<<<(BATCH * NH * NC * HD) / 256, 256>>>();
    // compressed attention + top-k selection (writes d_O = g0*out_c)
    cmp_attn_kernel<<<dim3(64, 8, 2), 256, 104192>>>();
    // selection branch (d_O += g1*out_s)
    sel_win_kernel<<<dim3(64, 8, 2), 256, 68608>>>(0);
    // window branch (d_O += g2*out_w)
    sel_win_kernel<<<dim3(64, 8, 2), 256, 68608>>>(1);
    // final projection y = d_O @ Wo
    gemm512<<<dim3(8, 128, 1), 256>>>(nullptr, Wo, nullptr, nullptr, y, 3);
}

// round 2
// speedup vs baseline: 2.2253x; 2.2253x over previous
#include <cuda_runtime.h>
#include <math.h>

#define BATCH   2
#define SEQ     4096
#define DMODEL  512
#define NH      8
#define HD      64
#define NC      128     // S / CB(32)
#define NS      64      // S / SB(64)
#define TOPK    16
#define NROWS   (BATCH*SEQ)   // 8192

// ---------------- scratch (device globals; no allocations) ----------------
__device__ float d_Q[NROWS*DMODEL];
__device__ float d_K[NROWS*DMODEL];
__device__ float d_V[NROWS*DMODEL];
__device__ float d_O[NROWS*DMODEL];
__device__ float d_KC[BATCH*NH*NC*HD];
__device__ float d_VC[BATCH*NH*NC*HD];
__device__ float d_G[NROWS*3];
__device__ int   d_SEL[BATCH*NH*NS*TOPK];

// ---------------- generic 512-K / 512-N fp32 GEMM -------------------------
__global__ __launch_bounds__(256) void gemm512(const float* __restrict__ Aext,
    const float* __restrict__ B0, const float* __restrict__ B1,
    const float* __restrict__ B2, float* __restrict__ Cext, int modeBase)
{
    int mode = modeBase + blockIdx.z;
    const float* A  = (mode == 3) ? d_O : Aext;
    const float* Bm = (mode == 1) ? B1 : (mode == 2) ? B2 : B0;
    float* C = (mode == 0) ? d_Q : (mode == 1) ? d_K : (mode == 2) ? d_V : Cext;

    __shared__ float As[16][68];
    __shared__ float Bs[16][68];
    int tid = threadIdx.x;
    int tx = tid & 15, ty = tid >> 4;
    int m0 = blockIdx.y * 64, n0 = blockIdx.x * 64;
    float acc[4][4];
#pragma unroll
    for (int i = 0; i < 4; i++)
#pragma unroll
        for (int j = 0; j < 4; j++) acc[i][j] = 0.f;

    int la_m = (tid * 4) >> 4, la_k = (tid * 4) & 15;
    int lb_k = (tid * 4) >> 6, lb_n = (tid * 4) & 63;

    for (int k0 = 0; k0 < 512; k0 += 16) {
        float4 av = *(const float4*)(A + (size_t)(m0 + la_m) * 512 + k0 + la_k);
        As[la_k + 0][la_m] = av.x; As[la_k + 1][la_m] = av.y;
        As[la_k + 2][la_m] = av.z; As[la_k + 3][la_m] = av.w;
        *(float4*)(&Bs[lb_k][lb_n]) =
            *(const float4*)(Bm + (size_t)(k0 + lb_k) * 512 + n0 + lb_n);
        __syncthreads();
#pragma unroll
        for (int kk = 0; kk < 16; kk++) {
            float4 a4 = *(const float4*)(&As[kk][ty * 4]);
            float4 b4 = *(const float4*)(&Bs[kk][tx * 4]);
            float ar[4] = {a4.x, a4.y, a4.z, a4.w};
            float br[4] = {b4.x, b4.y, b4.z, b4.w};
#pragma unroll
            for (int i = 0; i < 4; i++)
#pragma unroll
                for (int j = 0; j < 4; j++) acc[i][j] += ar[i] * br[j];
        }
        __syncthreads();
    }
#pragma unroll
    for (int i = 0; i < 4; i++) {
        float4 v = make_float4(acc[i][0], acc[i][1], acc[i][2], acc[i][3]);
        *(float4*)(C + (size_t)(m0 + ty * 4 + i) * 512 + n0 + tx * 4) = v;
    }
}

// ---------------- gate: sigmoid(x @ Wg), Wg is [512,3] --------------------
__global__ __launch_bounds__(128) void gate_kernel(const float* __restrict__ x,
                                                   const float* __restrict__ Wg)
{
    int row = blockIdx.x;
    int tid = threadIdx.x, lane = tid & 31, w = tid >> 5;
    float p0 = 0, p1 = 0, p2 = 0;
    for (int d = tid; d < 512; d += 128) {
        float xv = x[(size_t)row * 512 + d];
        p0 += xv * Wg[d * 3 + 0];
        p1 += xv * Wg[d * 3 + 1];
        p2 += xv * Wg[d * 3 + 2];
    }
#pragma unroll
    for (int o = 16; o; o >>= 1) {
        p0 += __shfl_xor_sync(0xffffffffu, p0, o);
        p1 += __shfl_xor_sync(0xffffffffu, p1, o);
        p2 += __shfl_xor_sync(0xffffffffu, p2, o);
    }
    __shared__ float red[3][4];
    if (lane == 0) { red[0][w] = p0; red[1][w] = p1; red[2][w] = p2; }
    __syncthreads();
    if (tid < 3) {
        float v = red[tid][0] + red[tid][1] + red[tid][2] + red[tid][3];
        d_G[row * 3 + tid] = 1.f / (1.f + expf(-v));
    }
}

// ---------------- compressed K/V: mean over CB=32 rows ---------------------
__global__ __launch_bounds__(256) void compress_kernel()
{
    int idx = blockIdx.x * 256 + threadIdx.x;      // 2^17 threads
    int d = idx & 63, n = (idx >> 6) & 127, h = (idx >> 13) & 7, b = idx >> 16;
    const float* kp = d_K + (size_t)(b * SEQ + n * 32) * 512 + h * 64 + d;
    const float* vp = d_V + (size_t)(b * SEQ + n * 32) * 512 + h * 64 + d;
    float ks = 0, vs = 0;
#pragma unroll
    for (int r = 0; r < 32; r++) { ks += kp[r * 512]; vs += vp[r * 512]; }
    d_KC[idx] = ks * (1.f / 32.f);
    d_VC[idx] = vs * (1.f / 32.f);
}

// ---------------- compressed attention + importance + top-k ----------------
__global__ __launch_bounds__(256) void cmp_attn_kernel()
{
    extern __shared__ float sm[];
    float* kc   = sm;                 // 128*65
    float* vc   = kc  + 128 * 65;     // 128*65
    float* qs   = vc  + 128 * 65;     // 64*65
    float* pcs  = qs  + 64 * 65;      // 8*128 (per-warp probs)
    float* imps = pcs + 8 * 128;      // 64*65 (per-query block importance)
    float* impb = imps + 64 * 65;     // 64

    int g = blockIdx.x, h = blockIdx.y, b = blockIdx.z;
    int tid = threadIdx.x, lane = tid & 31, w = tid >> 5;

    int cbase = ((b * NH + h) * NC) * HD;
    for (int i = tid; i < NC * HD; i += 256) {
        int n = i >> 6, d = i & 63;
        kc[n * 65 + d] = d_KC[cbase + i];
        vc[n * 65 + d] = d_VC[cbase + i];
    }
    for (int i = tid; i < 64 * 64; i += 256) {
        int r = i >> 6, d = i & 63;
        qs[r * 65 + d] = d_Q[(size_t)(b * SEQ + g * 64 + r) * 512 + h * 64 + d];
    }
    __syncthreads();

    for (int itq = 0; itq < 8; itq++) {
        int qr = w * 8 + itq;
        int pos = g * 64 + qr;
        int nvalid = (pos >= 31) ? ((pos - 31) >> 5) + 1 : 0;
        float s[4];
#pragma unroll
        for (int kk = 0; kk < 4; kk++) {
            int c = lane + 32 * kk;
            if (c < nvalid) {
                float a = 0;
#pragma unroll
                for (int d = 0; d < 64; d++) a += qs[qr * 65 + d] * kc[c * 65 + d];
                s[kk] = a * 0.125f;
            } else s[kk] = -1e30f;
        }
        float mx = fmaxf(fmaxf(s[0], s[1]), fmaxf(s[2], s[3]));
#pragma unroll
        for (int o = 16; o; o >>= 1) mx = fmaxf(mx, __shfl_xor_sync(0xffffffffu, mx, o));
        float e[4], ls = 0;
#pragma unroll
        for (int kk = 0; kk < 4; kk++) {
            e[kk] = (nvalid > 0) ? __expf(s[kk] - mx) : 0.f;
            ls += e[kk];
        }
#pragma unroll
        for (int o = 16; o; o >>= 1) ls += __shfl_xor_sync(0xffffffffu, ls, o);
        float inv = (nvalid > 0) ? 1.f / ls : 0.f;
#pragma unroll
        for (int kk = 0; kk < 4; kk++) pcs[w * 128 + lane + 32 * kk] = e[kk] * inv;
        __syncwarp();
#pragma unroll
        for (int jj = 0; jj < 2; jj++) {
            int j = lane + 32 * jj;
            imps[qr * 65 + j] = pcs[w * 128 + 2 * j] + pcs[w * 128 + 2 * j + 1];
        }
        float o0 = 0, o1 = 0;
        for (int c = 0; c < 128; c++) {
            float p = pcs[w * 128 + c];
            o0 += p * vc[c * 65 + lane];
            o1 += p * vc[c * 65 + lane + 32];
        }
        float g0 = d_G[(b * SEQ + pos) * 3 + 0];
        size_t ob = (size_t)(b * SEQ + pos) * 512 + h * 64;
        d_O[ob + lane]      = g0 * o0;
        d_O[ob + lane + 32] = g0 * o1;
        __syncwarp();
    }
    __syncthreads();
    if (tid < 64) {
        float v = 0;
        for (int q = 0; q < 64; q++) v += imps[q * 65 + tid];
        impb[tid] = v;
    }
    __syncthreads();
    if (w == 0) {
        int j0 = lane, j1 = lane + 32;
        float v0 = (j0 <= g) ? impb[j0] + (j0 == g ? 1e9f : 0.f) : -1e30f;
        float v1 = (j1 <= g) ? impb[j1] + (j1 == g ? 1e9f : 0.f) : -1e30f;
        int selbase = ((b * NH + h) * NS + g) * TOPK;
        for (int r = 0; r < TOPK; r++) {
            float bv; int bi;
            if (v0 >= v1) { bv = v0; bi = j0; } else { bv = v1; bi = j1; }
#pragma unroll
            for (int o = 16; o; o >>= 1) {
                float ov = __shfl_xor_sync(0xffffffffu, bv, o);
                int   oi = __shfl_xor_sync(0xffffffffu, bi, o);
                if (ov > bv || (ov == bv && oi < bi)) { bv = ov; bi = oi; }
            }
            if (lane == 0) d_SEL[selbase + r] = bi;
            if (bi == j0) v0 = -3e30f;
            if (bi == j1) v1 = -3e30f;
        }
    }
}

// ---------------- selection / window flash attention (register tiled) ------
// thread (ty = tid>>4, tx = tid&15) owns a 4x4 micro-tile:
//   QK phase: S[ty*4+i][tx*4+j]  (rows=queries, cols=keys)
//   PV phase: O[ty*4+i][tx*4+j]  (rows=queries, cols=dims)
// row-softmax state (m, l) replicated across the 16 tx-lanes of a ty-group
// (one half-warp), reduced via shfl_xor 1/2/4/8.
// mode 0: 16 selected 64-key blocks; mode 1: 9 window tiles g-8..g.
__global__ __launch_bounds__(256) void sel_win_kernel(int mode)
{
    extern __shared__ float sm[];
    float* qs = sm;               // 64*65  [query][dim]
    float* Ks = qs + 64 * 65;     // 64*65  [key][dim]
    float* Vs = Ks + 64 * 65;     // 64*65  [key][dim]
    float* ps = Vs + 64 * 65;     // 64*65  [query][key]

    int g = blockIdx.x, h = blockIdx.y, b = blockIdx.z;
    int tid = threadIdx.x;
    int tx = tid & 15, ty = tid >> 4;
    int qbase = g * 64;

    // load Q tile (float4 global read, scalar smem store stride 65)
    for (int i = tid; i < 1024; i += 256) {
        int r = i >> 4, d4 = (i & 15) * 4;
        float4 v = *(const float4*)(d_Q + (size_t)(b * SEQ + qbase + r) * 512 + h * 64 + d4);
        qs[r * 65 + d4 + 0] = v.x; qs[r * 65 + d4 + 1] = v.y;
        qs[r * 65 + d4 + 2] = v.z; qs[r * 65 + d4 + 3] = v.w;
    }

    float acc[4][4];
#pragma unroll
    for (int i = 0; i < 4; i++)
#pragma unroll
        for (int j = 0; j < 4; j++) acc[i][j] = 0.f;
    float m[4], l[4];
#pragma unroll
    for (int i = 0; i < 4; i++) { m[i] = -1e30f; l[i] = 0.f; }

    int niter = mode ? 9 : TOPK;
    int selbase = ((b * NH + h) * NS + g) * TOPK;

    for (int it = 0; it < niter; it++) {
        int kb = mode ? (g - 8 + it) : d_SEL[selbase + it];
        if (kb < 0) continue;                 // uniform across block
        __syncthreads();                      // everyone done with prev K/V
        size_t kbase = (size_t)(b * SEQ + kb * 64) * 512 + h * 64;
        for (int i = tid; i < 1024; i += 256) {
            int r = i >> 4, d4 = (i & 15) * 4;
            float4 kv = *(const float4*)(d_K + kbase + (size_t)r * 512 + d4);
            float4 vv = *(const float4*)(d_V + kbase + (size_t)r * 512 + d4);
            Ks[r * 65 + d4 + 0] = kv.x; Ks[r * 65 + d4 + 1] = kv.y;
            Ks[r * 65 + d4 + 2] = kv.z; Ks[r * 65 + d4 + 3] = kv.w;
            Vs[r * 65 + d4 + 0] = vv.x; Vs[r * 65 + d4 + 1] = vv.y;
            Vs[r * 65 + d4 + 2] = vv.z; Vs[r * 65 + d4 + 3] = vv.w;
        }
        __syncthreads();

        // ---- QK^T micro-GEMM: 4x4 per thread ----
        float s[4][4];
#pragma unroll
        for (int i = 0; i < 4; i++)
#pragma unroll
            for (int j = 0; j < 4; j++) s[i][j] = 0.f;
#pragma unroll 4
        for (int d = 0; d < 64; d++) {
            float a[4], kr[4];
#pragma unroll
            for (int i = 0; i < 4; i++) a[i] = qs[(ty * 4 + i) * 65 + d];
#pragma unroll
            for (int j = 0; j < 4; j++) kr[j] = Ks[(tx * 4 + j) * 65 + d];
#pragma unroll
            for (int i = 0; i < 4; i++)
#pragma unroll
                for (int j = 0; j < 4; j++) s[i][j] += a[i] * kr[j];
        }

        // mask + scale
#pragma unroll
        for (int i = 0; i < 4; i++) {
            int qp = qbase + ty * 4 + i;
#pragma unroll
            for (int j = 0; j < 4; j++) {
                int kp = kb * 64 + tx * 4 + j;
                bool valid = (kp <= qp) && (!mode || (kp + 512 > qp));
                s[i][j] = valid ? s[i][j] * 0.125f : -1e30f;
            }
        }

        // row max (reduce over 16 tx lanes, xor<=8 stays in half-warp)
        float rm[4];
#pragma unroll
        for (int i = 0; i < 4; i++) {
            rm[i] = fmaxf(fmaxf(s[i][0], s[i][1]), fmaxf(s[i][2], s[i][3]));
#pragma unroll
            for (int o = 8; o; o >>= 1)
                rm[i] = fmaxf(rm[i], __shfl_xor_sync(0xffffffffu, rm[i], o));
        }

        float rowsum[4];
#pragma unroll
        for (int i = 0; i < 4; i++) {
            float mnew = fmaxf(m[i], rm[i]);
            float corr = __expf(m[i] - mnew);   // both -1e30 -> exp(0)=1, acc=0
            float rs = 0.f;
#pragma unroll
            for (int j = 0; j < 4; j++) {
                float p = (s[i][j] > -1e29f) ? __expf(s[i][j] - mnew) : 0.f;
                s[i][j] = p;
                rs += p;
            }
#pragma unroll
            for (int o = 8; o; o >>= 1)
                rs += __shfl_xor_sync(0xffffffffu, rs, o);
            rowsum[i] = rs;
#pragma unroll
            for (int j = 0; j < 4; j++) acc[i][j] *= corr;
            l[i] = l[i] * corr + rowsum[i];
            m[i] = mnew;
        }

        // stash P (warp-local: a query row is owned by one half-warp)
#pragma unroll
        for (int i = 0; i < 4; i++)
#pragma unroll
            for (int j = 0; j < 4; j++)
                ps[(ty * 4 + i) * 65 + tx * 4 + j] = s[i][j];
        __syncwarp();

        // ---- P*V micro-GEMM: 4x4 per thread (tx now indexes dims) ----
#pragma unroll 2
        for (int k4 = 0; k4 < 64; k4 += 4) {
            float pr[4][4];
#pragma unroll
            for (int i = 0; i < 4; i++)
#pragma unroll
                for (int kk = 0; kk < 4; kk++)
                    pr[i][kk] = ps[(ty * 4 + i) * 65 + k4 + kk];
#pragma unroll
            for (int kk = 0; kk < 4; kk++) {
                float vv[4];
#pragma unroll
                for (int j = 0; j < 4; j++)
                    vv[j] = Vs[(k4 + kk) * 65 + tx * 4 + j];
#pragma unroll
                for (int i = 0; i < 4; i++)
#pragma unroll
                    for (int j = 0; j < 4; j++)
                        acc[i][j] += pr[i][kk] * vv[j];
            }
        }
        __syncwarp();
    }

    // epilogue: d_O += gate * acc / l
#pragma unroll
    for (int i = 0; i < 4; i++) {
        int qp = qbase + ty * 4 + i;
        float gv = d_G[(b * SEQ + qp) * 3 + (mode ? 2 : 1)];
        float inv = gv / l[i];
        size_t ob = (size_t)(b * SEQ + qp) * 512 + h * 64 + tx * 4;
        float4 cur = *(float4*)(d_O + ob);
        cur.x += acc[i][0] * inv;
        cur.y += acc[i][1] * inv;
        cur.z += acc[i][2] * inv;
        cur.w += acc[i][3] * inv;
        *(float4*)(d_O + ob) = cur;
    }
}

// ---------------------------------------------------------------------------
extern "C" void kernel_launch(void* const* d_in, const int* in_sizes, int n_in,
                              void* d_out, int out_size)
{
    const float* x  = (const float*)d_in[0];
    const float* Wq = (const float*)d_in[1];
    const float* Wk = (const float*)d_in[2];
    const float* Wv = (const float*)d_in[3];
    const float* Wo = (const float*)d_in[4];
    const float* Wg = (const float*)d_in[5];
    float* y = (float*)d_out;

    cudaFuncSetAttribute(cmp_attn_kernel,
                         cudaFuncAttributeMaxDynamicSharedMemorySize, 104192);
    cudaFuncSetAttribute(sel_win_kernel,
                         cudaFuncAttributeMaxDynamicSharedMemorySize, 66560);

    gemm512<<<dim3(8, 128, 3), 256>>>(x, Wq, Wk, Wv, nullptr, 0);
    gate_kernel<<<NROWS, 128>>>(x, Wg);
    compress_kernel<<<(BATCH * NH * NC * HD) / 256, 256>>>();
    cmp_attn_kernel<<<dim3(64, 8, 2), 256, 104192>>>();
    sel_win_kernel<<<dim3(64, 8, 2), 256, 66560>>>(0);
    sel_win_kernel<<<dim3(64, 8, 2), 256, 66560>>>(1);
    gemm512<<<dim3(8, 128, 1), 256>>>(nullptr, Wo, nullptr, nullptr, y, 3);
}

// round 3
// speedup vs baseline: 5.0271x; 2.2591x over previous
#include <cuda_runtime.h>
#include <math.h>
#include <stdint.h>

#define BATCH   2
#define SEQ     4096
#define DMODEL  512
#define NH      8
#define HD      64
#define NC      128
#define NS      64
#define TOPK    16
#define NROWS   (BATCH*SEQ)

// ---------------- scratch ----------------
__device__ float d_Q[NROWS*DMODEL];
__device__ float d_K[NROWS*DMODEL];
__device__ float d_V[NROWS*DMODEL];
__device__ float d_O[NROWS*DMODEL];
__device__ float d_KC[BATCH*NH*NC*HD];
__device__ float d_VC[BATCH*NH*NC*HD];
__device__ float d_G[NROWS*3];
__device__ int   d_SEL[BATCH*NH*NS*TOPK];

// ---------------- tf32 helpers ----------------
__device__ __forceinline__ float ftf(float x) {
    uint32_t u;
    asm("cvt.rna.tf32.f32 %0, %1;" : "=r"(u) : "f"(x));
    return __uint_as_float(u);
}
__device__ __forceinline__ void mma_tf32(float* c, const uint32_t* a, const uint32_t* b) {
    asm volatile(
        "mma.sync.aligned.m16n8k8.row.col.f32.tf32.tf32.f32 "
        "{%0,%1,%2,%3},{%4,%5,%6,%7},{%8,%9},{%0,%1,%2,%3};\n"
        : "+f"(c[0]), "+f"(c[1]), "+f"(c[2]), "+f"(c[3])
        : "r"(a[0]), "r"(a[1]), "r"(a[2]), "r"(a[3]), "r"(b[0]), "r"(b[1]));
}
#define U(x) __float_as_uint(x)

// ---------------- tf32 tensor-core GEMM: [8192x512] @ [512x512] -----------
// block tile 128x64, BK=16, 8 warps (4m x 2n), warp tile 32x32
#define GPA 20
#define GPB 72
__global__ __launch_bounds__(256) void gemm512_tc(const float* __restrict__ Aext,
    const float* __restrict__ B0, const float* __restrict__ B1,
    const float* __restrict__ B2, float* __restrict__ Cext, int modeBase)
{
    int mode = modeBase + blockIdx.z;
    const float* A  = (mode == 3) ? d_O : Aext;
    const float* Bm = (mode == 1) ? B1 : (mode == 2) ? B2 : B0;
    float* C = (mode == 0) ? d_Q : (mode == 1) ? d_K : (mode == 2) ? d_V : Cext;

    __shared__ float As[128 * GPA];   // [m][k] pad 20
    __shared__ float Bs[16 * GPB];    // [k][n] pad 72

    int tid = threadIdx.x, lane = tid & 31, w = tid >> 5;
    int grp = lane >> 2, t4 = lane & 3;
    int wm = w & 3, wn = w >> 2;
    int m0 = blockIdx.y * 128, n0 = blockIdx.x * 64;

    float acc[2][4][4];
#pragma unroll
    for (int mt = 0; mt < 2; mt++)
#pragma unroll
        for (int nt = 0; nt < 4; nt++)
#pragma unroll
            for (int r = 0; r < 4; r++) acc[mt][nt][r] = 0.f;

    for (int k0 = 0; k0 < 512; k0 += 16) {
#pragma unroll
        for (int ii = 0; ii < 2; ii++) {
            int i = tid + ii * 256;
            int r = i >> 2, kk = (i & 3) * 4;
            float4 v = *(const float4*)(A + (size_t)(m0 + r) * 512 + k0 + kk);
            float4 t = make_float4(ftf(v.x), ftf(v.y), ftf(v.z), ftf(v.w));
            *(float4*)(&As[r * GPA + kk]) = t;
        }
        {
            int r = tid >> 4, c4 = (tid & 15) * 4;
            float4 v = *(const float4*)(Bm + (size_t)(k0 + r) * 512 + n0 + c4);
            float4 t = make_float4(ftf(v.x), ftf(v.y), ftf(v.z), ftf(v.w));
            *(float4*)(&Bs[r * GPB + c4]) = t;
        }
        __syncthreads();
#pragma unroll
        for (int ks = 0; ks < 2; ks++) {
            int kb = ks * 8;
            uint32_t af[2][4], bf[4][2];
#pragma unroll
            for (int mt = 0; mt < 2; mt++) {
                int row = wm * 32 + mt * 16 + grp;
                af[mt][0] = U(As[row * GPA + kb + t4]);
                af[mt][1] = U(As[(row + 8) * GPA + kb + t4]);
                af[mt][2] = U(As[row * GPA + kb + t4 + 4]);
                af[mt][3] = U(As[(row + 8) * GPA + kb + t4 + 4]);
            }
#pragma unroll
            for (int nt = 0; nt < 4; nt++) {
                int col = wn * 32 + nt * 8 + grp;
                bf[nt][0] = U(Bs[(kb + t4) * GPB + col]);
                bf[nt][1] = U(Bs[(kb + t4 + 4) * GPB + col]);
            }
#pragma unroll
            for (int mt = 0; mt < 2; mt++)
#pragma unroll
                for (int nt = 0; nt < 4; nt++)
                    mma_tf32(acc[mt][nt], af[mt], bf[nt]);
        }
        __syncthreads();
    }
#pragma unroll
    for (int mt = 0; mt < 2; mt++)
#pragma unroll
        for (int nt = 0; nt < 4; nt++) {
            int row = m0 + wm * 32 + mt * 16 + grp;
            int col = n0 + wn * 32 + nt * 8 + 2 * t4;
            *(float2*)(C + (size_t)row * 512 + col) =
                make_float2(acc[mt][nt][0], acc[mt][nt][1]);
            *(float2*)(C + (size_t)(row + 8) * 512 + col) =
                make_float2(acc[mt][nt][2], acc[mt][nt][3]);
        }
}

// ---------------- gate ----------------
__global__ __launch_bounds__(128) void gate_kernel(const float* __restrict__ x,
                                                   const float* __restrict__ Wg)
{
    int row = blockIdx.x;
    int tid = threadIdx.x, lane = tid & 31, w = tid >> 5;
    float p0 = 0, p1 = 0, p2 = 0;
    for (int d = tid; d < 512; d += 128) {
        float xv = x[(size_t)row * 512 + d];
        p0 += xv * Wg[d * 3 + 0];
        p1 += xv * Wg[d * 3 + 1];
        p2 += xv * Wg[d * 3 + 2];
    }
#pragma unroll
    for (int o = 16; o; o >>= 1) {
        p0 += __shfl_xor_sync(0xffffffffu, p0, o);
        p1 += __shfl_xor_sync(0xffffffffu, p1, o);
        p2 += __shfl_xor_sync(0xffffffffu, p2, o);
    }
    __shared__ float red[3][4];
    if (lane == 0) { red[0][w] = p0; red[1][w] = p1; red[2][w] = p2; }
    __syncthreads();
    if (tid < 3) {
        float v = red[tid][0] + red[tid][1] + red[tid][2] + red[tid][3];
        d_G[row * 3 + tid] = 1.f / (1.f + expf(-v));
    }
}

// ---------------- compressed K/V means ----------------
__global__ __launch_bounds__(256) void compress_kernel()
{
    int idx = blockIdx.x * 256 + threadIdx.x;
    int d = idx & 63, n = (idx >> 6) & 127, h = (idx >> 13) & 7, b = idx >> 16;
    const float* kp = d_K + (size_t)(b * SEQ + n * 32) * 512 + h * 64 + d;
    const float* vp = d_V + (size_t)(b * SEQ + n * 32) * 512 + h * 64 + d;
    float ks = 0, vs = 0;
#pragma unroll
    for (int r = 0; r < 32; r++) { ks += kp[r * 512]; vs += vp[r * 512]; }
    d_KC[idx] = ks * (1.f / 32.f);
    d_VC[idx] = vs * (1.f / 32.f);
}

// ---------------- compressed attention + top-k (512 threads now) ----------
__global__ __launch_bounds__(512) void cmp_attn_kernel()
{
    extern __shared__ float sm[];
    float* kc   = sm;                 // 128*65
    float* vc   = kc  + 128 * 65;     // 128*65
    float* qs   = vc  + 128 * 65;     // 64*65
    float* pcs  = qs  + 64 * 65;      // 16*128
    float* imps = pcs + 16 * 128;     // 64*65
    float* impb = imps + 64 * 65;     // 64

    int g = blockIdx.x, h = blockIdx.y, b = blockIdx.z;
    int tid = threadIdx.x, lane = tid & 31, w = tid >> 5;

    int cbase = ((b * NH + h) * NC) * HD;
    for (int i = tid; i < NC * HD; i += 512) {
        int n = i >> 6, d = i & 63;
        kc[n * 65 + d] = d_KC[cbase + i];
        vc[n * 65 + d] = d_VC[cbase + i];
    }
    for (int i = tid; i < 64 * 64; i += 512) {
        int r = i >> 6, d = i & 63;
        qs[r * 65 + d] = d_Q[(size_t)(b * SEQ + g * 64 + r) * 512 + h * 64 + d];
    }
    __syncthreads();

    for (int itq = 0; itq < 4; itq++) {
        int qr = w * 4 + itq;
        int pos = g * 64 + qr;
        int nvalid = (pos >= 31) ? ((pos - 31) >> 5) + 1 : 0;
        float s[4];
#pragma unroll
        for (int kk = 0; kk < 4; kk++) {
            int c = lane + 32 * kk;
            if (c < nvalid) {
                float a = 0;
#pragma unroll
                for (int d = 0; d < 64; d++) a += qs[qr * 65 + d] * kc[c * 65 + d];
                s[kk] = a * 0.125f;
            } else s[kk] = -1e30f;
        }
        float mx = fmaxf(fmaxf(s[0], s[1]), fmaxf(s[2], s[3]));
#pragma unroll
        for (int o = 16; o; o >>= 1) mx = fmaxf(mx, __shfl_xor_sync(0xffffffffu, mx, o));
        float e[4], ls = 0;
#pragma unroll
        for (int kk = 0; kk < 4; kk++) {
            e[kk] = (nvalid > 0) ? __expf(s[kk] - mx) : 0.f;
            ls += e[kk];
        }
#pragma unroll
        for (int o = 16; o; o >>= 1) ls += __shfl_xor_sync(0xffffffffu, ls, o);
        float inv = (nvalid > 0) ? 1.f / ls : 0.f;
#pragma unroll
        for (int kk = 0; kk < 4; kk++) pcs[w * 128 + lane + 32 * kk] = e[kk] * inv;
        __syncwarp();
#pragma unroll
        for (int jj = 0; jj < 2; jj++) {
            int j = lane + 32 * jj;
            imps[qr * 65 + j] = pcs[w * 128 + 2 * j] + pcs[w * 128 + 2 * j + 1];
        }
        float o0 = 0, o1 = 0;
        for (int c = 0; c < 128; c++) {
            float p = pcs[w * 128 + c];
            o0 += p * vc[c * 65 + lane];
            o1 += p * vc[c * 65 + lane + 32];
        }
        float g0 = d_G[(b * SEQ + pos) * 3 + 0];
        size_t ob = (size_t)(b * SEQ + pos) * 512 + h * 64;
        d_O[ob + lane]      = g0 * o0;
        d_O[ob + lane + 32] = g0 * o1;
        __syncwarp();
    }
    __syncthreads();
    if (tid < 64) {
        float v = 0;
        for (int q = 0; q < 64; q++) v += imps[q * 65 + tid];
        impb[tid] = v;
    }
    __syncthreads();
    if (w == 0) {
        int j0 = lane, j1 = lane + 32;
        float v0 = (j0 <= g) ? impb[j0] + (j0 == g ? 1e9f : 0.f) : -1e30f;
        float v1 = (j1 <= g) ? impb[j1] + (j1 == g ? 1e9f : 0.f) : -1e30f;
        int selbase = ((b * NH + h) * NS + g) * TOPK;
        for (int r = 0; r < TOPK; r++) {
            float bv; int bi;
            if (v0 >= v1) { bv = v0; bi = j0; } else { bv = v1; bi = j1; }
#pragma unroll
            for (int o = 16; o; o >>= 1) {
                float ov = __shfl_xor_sync(0xffffffffu, bv, o);
                int   oi = __shfl_xor_sync(0xffffffffu, bi, o);
                if (ov > bv || (ov == bv && oi < bi)) { bv = ov; bi = oi; }
            }
            if (lane == 0) d_SEL[selbase + r] = bi;
            if (bi == j0) v0 = -3e30f;
            if (bi == j1) v1 = -3e30f;
        }
    }
}

// ---------------- selection / window flash attention (tf32 mma) ------------
// 8 warps: wm = w&1 (q rows 32*wm), wn = w>>1 (0..3).
// QK: warp S-tile 32q x 16key (2 m-tiles x 2 n-tiles), k=64 -> 8 k-steps.
// PV: warp O-tile 32q x 16d, A = P from smem, k=64 keys.
#define PK 68
#define PV 72
__global__ __launch_bounds__(256) void sel_win_kernel(int mode)
{
    extern __shared__ float sm[];
    float* qs   = sm;                 // 64*68
    float* Ks   = qs + 64 * PK;       // 64*68
    float* Vs   = Ks + 64 * PK;       // 64*72
    float* ps   = Vs + 64 * PV;       // 64*68
    float* redm = ps + 64 * PK;       // 64*4
    float* reds = redm + 64 * 4;      // 64*4

    int g = blockIdx.x, hh = blockIdx.y, b = blockIdx.z;
    int tid = threadIdx.x, lane = tid & 31, w = tid >> 5;
    int grp = lane >> 2, t4 = lane & 3;
    int wm = w & 1, wn = w >> 1;
    int qbase = g * 64;

    // load Q (tf32)
    for (int i = tid; i < 1024; i += 256) {
        int r = i >> 4, d4 = (i & 15) * 4;
        float4 v = *(const float4*)(d_Q + (size_t)(b * SEQ + qbase + r) * 512 + hh * 64 + d4);
        *(float4*)(&qs[r * PK + d4]) = make_float4(ftf(v.x), ftf(v.y), ftf(v.z), ftf(v.w));
    }

    float o[2][2][4];
#pragma unroll
    for (int mt = 0; mt < 2; mt++)
#pragma unroll
        for (int nt = 0; nt < 2; nt++)
#pragma unroll
            for (int r = 0; r < 4; r++) o[mt][nt][r] = 0.f;
    float mst[2][2], lst[2][2];
#pragma unroll
    for (int mt = 0; mt < 2; mt++)
#pragma unroll
        for (int hf = 0; hf < 2; hf++) { mst[mt][hf] = -1e30f; lst[mt][hf] = 0.f; }

    int niter = mode ? 9 : TOPK;
    int selbase = ((b * NH + hh) * NS + g) * TOPK;

    for (int it = 0; it < niter; it++) {
        int kb = mode ? (g - 8 + it) : d_SEL[selbase + it];
        if (kb < 0) continue;
        __syncthreads();
        size_t kbase = (size_t)(b * SEQ + kb * 64) * 512 + hh * 64;
        for (int i = tid; i < 1024; i += 256) {
            int r = i >> 4, d4 = (i & 15) * 4;
            float4 kv = *(const float4*)(d_K + kbase + (size_t)r * 512 + d4);
            float4 vv = *(const float4*)(d_V + kbase + (size_t)r * 512 + d4);
            *(float4*)(&Ks[r * PK + d4]) = make_float4(ftf(kv.x), ftf(kv.y), ftf(kv.z), ftf(kv.w));
            *(float4*)(&Vs[r * PV + d4]) = make_float4(ftf(vv.x), ftf(vv.y), ftf(vv.z), ftf(vv.w));
        }
        __syncthreads();

        // ---- QK^T via mma ----
        float s[2][2][4];
#pragma unroll
        for (int mt = 0; mt < 2; mt++)
#pragma unroll
            for (int nt = 0; nt < 2; nt++)
#pragma unroll
                for (int r = 0; r < 4; r++) s[mt][nt][r] = 0.f;
#pragma unroll
        for (int ks = 0; ks < 8; ks++) {
            int kk = ks * 8;
            uint32_t af[2][4], bf[2][2];
#pragma unroll
            for (int mt = 0; mt < 2; mt++) {
                int row = wm * 32 + mt * 16 + grp;
                af[mt][0] = U(qs[row * PK + kk + t4]);
                af[mt][1] = U(qs[(row + 8) * PK + kk + t4]);
                af[mt][2] = U(qs[row * PK + kk + t4 + 4]);
                af[mt][3] = U(qs[(row + 8) * PK + kk + t4 + 4]);
            }
#pragma unroll
            for (int nt = 0; nt < 2; nt++) {
                int key = wn * 16 + nt * 8 + grp;
                bf[nt][0] = U(Ks[key * PK + kk + t4]);
                bf[nt][1] = U(Ks[key * PK + kk + t4 + 4]);
            }
#pragma unroll
            for (int mt = 0; mt < 2; mt++)
#pragma unroll
                for (int nt = 0; nt < 2; nt++)
                    mma_tf32(s[mt][nt], af[mt], bf[nt]);
        }

        // mask + scale
#pragma unroll
        for (int mt = 0; mt < 2; mt++)
#pragma unroll
            for (int nt = 0; nt < 2; nt++)
#pragma unroll
                for (int r = 0; r < 4; r++) {
                    int qp = qbase + wm * 32 + mt * 16 + grp + (r >> 1) * 8;
                    int kp = kb * 64 + wn * 16 + nt * 8 + 2 * t4 + (r & 1);
                    bool valid = (kp <= qp) && (!mode || (kp + 512 > qp));
                    s[mt][nt][r] = valid ? s[mt][nt][r] * 0.125f : -1e30f;
                }

        // row-max partials (per warp over its 16 cols), cross-warp via smem
#pragma unroll
        for (int mt = 0; mt < 2; mt++)
#pragma unroll
            for (int hf = 0; hf < 2; hf++) {
                float rm = fmaxf(fmaxf(s[mt][0][2 * hf], s[mt][0][2 * hf + 1]),
                                 fmaxf(s[mt][1][2 * hf], s[mt][1][2 * hf + 1]));
                rm = fmaxf(rm, __shfl_xor_sync(0xffffffffu, rm, 1));
                rm = fmaxf(rm, __shfl_xor_sync(0xffffffffu, rm, 2));
                if (t4 == 0)
                    redm[(wm * 32 + mt * 16 + grp + hf * 8) * 4 + wn] = rm;
            }
        __syncthreads();

        float corr[2][2], mnew[2][2];
#pragma unroll
        for (int mt = 0; mt < 2; mt++)
#pragma unroll
            for (int hf = 0; hf < 2; hf++) {
                int row = wm * 32 + mt * 16 + grp + hf * 8;
                float gmax = fmaxf(fmaxf(redm[row * 4 + 0], redm[row * 4 + 1]),
                                   fmaxf(redm[row * 4 + 2], redm[row * 4 + 3]));
                float mn = fmaxf(mst[mt][hf], gmax);
                mnew[mt][hf] = mn;
                corr[mt][hf] = __expf(mst[mt][hf] - mn);
            }

        // p = exp(s - mnew); partial row sums + stash P to smem (tf32)
#pragma unroll
        for (int mt = 0; mt < 2; mt++)
#pragma unroll
            for (int hf = 0; hf < 2; hf++) {
                int rowl = wm * 32 + mt * 16 + grp + hf * 8;
                float mn = mnew[mt][hf];
                float rs = 0.f;
#pragma unroll
                for (int nt = 0; nt < 2; nt++) {
                    float p0 = __expf(s[mt][nt][2 * hf]     - mn);
                    float p1 = __expf(s[mt][nt][2 * hf + 1] - mn);
                    rs += p0 + p1;
                    int col = wn * 16 + nt * 8 + 2 * t4;
                    ps[rowl * PK + col]     = ftf(p0);
                    ps[rowl * PK + col + 1] = ftf(p1);
                }
                rs += __shfl_xor_sync(0xffffffffu, rs, 1);
                rs += __shfl_xor_sync(0xffffffffu, rs, 2);
                if (t4 == 0) reds[rowl * 4 + wn] = rs;
            }
        __syncthreads();

        // update l, rescale o
#pragma unroll
        for (int mt = 0; mt < 2; mt++)
#pragma unroll
            for (int hf = 0; hf < 2; hf++) {
                int row = wm * 32 + mt * 16 + grp + hf * 8;
                float ls = reds[row * 4 + 0] + reds[row * 4 + 1] +
                           reds[row * 4 + 2] + reds[row * 4 + 3];
                float cr = corr[mt][hf];
                lst[mt][hf] = lst[mt][hf] * cr + ls;
                mst[mt][hf] = mnew[mt][hf];
#pragma unroll
                for (int nt = 0; nt < 2; nt++) {
                    o[mt][nt][2 * hf]     *= cr;
                    o[mt][nt][2 * hf + 1] *= cr;
                }
            }

        // ---- P*V via mma ----
#pragma unroll
        for (int ks = 0; ks < 8; ks++) {
            int kk = ks * 8;
            uint32_t af[2][4], bf[2][2];
#pragma unroll
            for (int mt = 0; mt < 2; mt++) {
                int row = wm * 32 + mt * 16 + grp;
                af[mt][0] = U(ps[row * PK + kk + t4]);
                af[mt][1] = U(ps[(row + 8) * PK + kk + t4]);
                af[mt][2] = U(ps[row * PK + kk + t4 + 4]);
                af[mt][3] = U(ps[(row + 8) * PK + kk + t4 + 4]);
            }
#pragma unroll
            for (int nt = 0; nt < 2; nt++) {
                int dcol = wn * 16 + nt * 8 + grp;
                bf[nt][0] = U(Vs[(kk + t4) * PV + dcol]);
                bf[nt][1] = U(Vs[(kk + t4 + 4) * PV + dcol]);
            }
#pragma unroll
            for (int mt = 0; mt < 2; mt++)
#pragma unroll
                for (int nt = 0; nt < 2; nt++)
                    mma_tf32(o[mt][nt], af[mt], bf[nt]);
        }
    }

    // epilogue: d_O += gate * o / l
#pragma unroll
    for (int mt = 0; mt < 2; mt++)
#pragma unroll
        for (int hf = 0; hf < 2; hf++) {
            int qp = qbase + wm * 32 + mt * 16 + grp + hf * 8;
            float gv = d_G[(b * SEQ + qp) * 3 + (mode ? 2 : 1)];
            float inv = gv / lst[mt][hf];
#pragma unroll
            for (int nt = 0; nt < 2; nt++) {
                int dcol = wn * 16 + nt * 8 + 2 * t4;
                size_t ob = (size_t)(b * SEQ + qp) * 512 + hh * 64 + dcol;
                float2 cur = *(float2*)(d_O + ob);
                cur.x += o[mt][nt][2 * hf]     * inv;
                cur.y += o[mt][nt][2 * hf + 1] * inv;
                *(float2*)(d_O + ob) = cur;
            }
        }
}

// ---------------------------------------------------------------------------
extern "C" void kernel_launch(void* const* d_in, const int* in_sizes, int n_in,
                              void* d_out, int out_size)
{
    const float* x  = (const float*)d_in[0];
    const float* Wq = (const float*)d_in[1];
    const float* Wk = (const float*)d_in[2];
    const float* Wv = (const float*)d_in[3];
    const float* Wo = (const float*)d_in[4];
    const float* Wg = (const float*)d_in[5];
    float* y = (float*)d_out;

    cudaFuncSetAttribute(cmp_attn_kernel,
                         cudaFuncAttributeMaxDynamicSharedMemorySize, 108288);
    cudaFuncSetAttribute(sel_win_kernel,
                         cudaFuncAttributeMaxDynamicSharedMemorySize, 72704);

    gemm512_tc<<<dim3(8, 64, 3), 256>>>(x, Wq, Wk, Wv, nullptr, 0);
    gate_kernel<<<NROWS, 128>>>(x, Wg);
    compress_kernel<<<(BATCH * NH * NC * HD) / 256, 256>>>();
    cmp_attn_kernel<<<dim3(64, 8, 2), 512, 108288>>>();
    sel_win_kernel<<<dim3(64, 8, 2), 256, 72704>>>(0);
    sel_win_kernel<<<dim3(64, 8, 2), 256, 72704>>>(1);
    gemm512_tc<<<dim3(8, 64, 1), 256>>>(nullptr, Wo, nullptr, nullptr, y, 3);
}

// round 5
// speedup vs baseline: 5.8248x; 1.1587x over previous
#include <cuda_runtime.h>
#include <math.h>
#include <stdint.h>

#define BATCH   2
#define SEQ     4096
#define DMODEL  512
#define NH      8
#define HD      64
#define NC      128
#define NS      64
#define TOPK    16
#define NROWS   (BATCH*SEQ)

// ---------------- scratch ----------------
__device__ float d_Q[NROWS*DMODEL];
__device__ float d_K[NROWS*DMODEL];
__device__ float d_V[NROWS*DMODEL];
__device__ float d_O[NROWS*DMODEL];
__device__ float d_KC[BATCH*NH*NC*HD];
__device__ float d_VC[BATCH*NH*NC*HD];
__device__ float d_G[NROWS*3];
__device__ int   d_SEL[BATCH*NH*NS*TOPK];

// ---------------- tf32 helpers ----------------
__device__ __forceinline__ float ftf(float x) {
    uint32_t u;
    asm("cvt.rna.tf32.f32 %0, %1;" : "=r"(u) : "f"(x));
    return __uint_as_float(u);
}
__device__ __forceinline__ float4 ftf4(float4 v) {
    return make_float4(ftf(v.x), ftf(v.y), ftf(v.z), ftf(v.w));
}
__device__ __forceinline__ void mma_tf32(float* c, const uint32_t* a, const uint32_t* b) {
    asm volatile(
        "mma.sync.aligned.m16n8k8.row.col.f32.tf32.tf32.f32 "
        "{%0,%1,%2,%3},{%4,%5,%6,%7},{%8,%9},{%0,%1,%2,%3};\n"
        : "+f"(c[0]), "+f"(c[1]), "+f"(c[2]), "+f"(c[3])
        : "r"(a[0]), "r"(a[1]), "r"(a[2]), "r"(a[3]), "r"(b[0]), "r"(b[1]));
}
__device__ __forceinline__ void split_tf32(float x, uint32_t& hi, uint32_t& lo) {
    float h = ftf(x);
    hi = __float_as_uint(h);
    lo = __float_as_uint(ftf(x - h));
}
#define U(x) __float_as_uint(x)

// ---------------- tf32 tensor-core GEMM: [8192x512] @ [512x512] -----------
#define GPA 20
#define GPB 72
__global__ __launch_bounds__(256) void gemm512_tc(const float* __restrict__ Aext,
    const float* __restrict__ B0, const float* __restrict__ B1,
    const float* __restrict__ B2, float* __restrict__ Cext, int modeBase)
{
    int mode = modeBase + blockIdx.z;
    const float* A  = (mode == 3) ? d_O : Aext;
    const float* Bm = (mode == 1) ? B1 : (mode == 2) ? B2 : B0;
    float* C = (mode == 0) ? d_Q : (mode == 1) ? d_K : (mode == 2) ? d_V : Cext;

    __shared__ float As[128 * GPA];
    __shared__ float Bs[16 * GPB];

    int tid = threadIdx.x, lane = tid & 31, w = tid >> 5;
    int grp = lane >> 2, t4 = lane & 3;
    int wm = w & 3, wn = w >> 2;
    int m0 = blockIdx.y * 128, n0 = blockIdx.x * 64;

    float acc[2][4][4];
#pragma unroll
    for (int mt = 0; mt < 2; mt++)
#pragma unroll
        for (int nt = 0; nt < 4; nt++)
#pragma unroll
            for (int r = 0; r < 4; r++) acc[mt][nt][r] = 0.f;

    for (int k0 = 0; k0 < 512; k0 += 16) {
#pragma unroll
        for (int ii = 0; ii < 2; ii++) {
            int i = tid + ii * 256;
            int r = i >> 2, kk = (i & 3) * 4;
            float4 v = *(const float4*)(A + (size_t)(m0 + r) * 512 + k0 + kk);
            *(float4*)(&As[r * GPA + kk]) = ftf4(v);
        }
        {
            int r = tid >> 4, c4 = (tid & 15) * 4;
            float4 v = *(const float4*)(Bm + (size_t)(k0 + r) * 512 + n0 + c4);
            *(float4*)(&Bs[r * GPB + c4]) = ftf4(v);
        }
        __syncthreads();
#pragma unroll
        for (int ks = 0; ks < 2; ks++) {
            int kb = ks * 8;
            uint32_t af[2][4], bf[4][2];
#pragma unroll
            for (int mt = 0; mt < 2; mt++) {
                int row = wm * 32 + mt * 16 + grp;
                af[mt][0] = U(As[row * GPA + kb + t4]);
                af[mt][1] = U(As[(row + 8) * GPA + kb + t4]);
                af[mt][2] = U(As[row * GPA + kb + t4 + 4]);
                af[mt][3] = U(As[(row + 8) * GPA + kb + t4 + 4]);
            }
#pragma unroll
            for (int nt = 0; nt < 4; nt++) {
                int col = wn * 32 + nt * 8 + grp;
                bf[nt][0] = U(Bs[(kb + t4) * GPB + col]);
                bf[nt][1] = U(Bs[(kb + t4 + 4) * GPB + col]);
            }
#pragma unroll
            for (int mt = 0; mt < 2; mt++)
#pragma unroll
                for (int nt = 0; nt < 4; nt++)
                    mma_tf32(acc[mt][nt], af[mt], bf[nt]);
        }
        __syncthreads();
    }
#pragma unroll
    for (int mt = 0; mt < 2; mt++)
#pragma unroll
        for (int nt = 0; nt < 4; nt++) {
            int row = m0 + wm * 32 + mt * 16 + grp;
            int col = n0 + wn * 32 + nt * 8 + 2 * t4;
            *(float2*)(C + (size_t)row * 512 + col) =
                make_float2(acc[mt][nt][0], acc[mt][nt][1]);
            *(float2*)(C + (size_t)(row + 8) * 512 + col) =
                make_float2(acc[mt][nt][2], acc[mt][nt][3]);
        }
}

// ---------------- gate ----------------
__global__ __launch_bounds__(128) void gate_kernel(const float* __restrict__ x,
                                                   const float* __restrict__ Wg)
{
    int row = blockIdx.x;
    int tid = threadIdx.x, lane = tid & 31, w = tid >> 5;
    float p0 = 0, p1 = 0, p2 = 0;
    for (int d = tid; d < 512; d += 128) {
        float xv = x[(size_t)row * 512 + d];
        p0 += xv * Wg[d * 3 + 0];
        p1 += xv * Wg[d * 3 + 1];
        p2 += xv * Wg[d * 3 + 2];
    }
#pragma unroll
    for (int o = 16; o; o >>= 1) {
        p0 += __shfl_xor_sync(0xffffffffu, p0, o);
        p1 += __shfl_xor_sync(0xffffffffu, p1, o);
        p2 += __shfl_xor_sync(0xffffffffu, p2, o);
    }
    __shared__ float red[3][4];
    if (lane == 0) { red[0][w] = p0; red[1][w] = p1; red[2][w] = p2; }
    __syncthreads();
    if (tid < 3) {
        float v = red[tid][0] + red[tid][1] + red[tid][2] + red[tid][3];
        d_G[row * 3 + tid] = 1.f / (1.f + expf(-v));
    }
}

// ---------------- compressed K/V means ----------------
__global__ __launch_bounds__(256) void compress_kernel()
{
    int idx = blockIdx.x * 256 + threadIdx.x;
    int d = idx & 63, n = (idx >> 6) & 127, h = (idx >> 13) & 7, b = idx >> 16;
    const float* kp = d_K + (size_t)(b * SEQ + n * 32) * 512 + h * 64 + d;
    const float* vp = d_V + (size_t)(b * SEQ + n * 32) * 512 + h * 64 + d;
    float ks = 0, vs = 0;
#pragma unroll
    for (int r = 0; r < 32; r++) { ks += kp[r * 512]; vs += vp[r * 512]; }
    d_KC[idx] = ks * (1.f / 32.f);
    d_VC[idx] = vs * (1.f / 32.f);
}

// ---------------- compressed attention + top-k (3xTF32 QK for selection) --
// QK scores feed top-k (discrete!) -> 3xTF32 split gives ~fp32 accuracy.
// PV (out_c) is a smooth path -> single tf32.
#define CQ 68
#define CK 72
#define CS 132
__global__ __launch_bounds__(256) void cmp_attn_mma()
{
    extern __shared__ float sm[];
    float* qs   = sm;                  // 64*68  (raw fp32 Q)
    float* kv   = qs + 64 * CQ;        // 128*72 (raw fp32 Kc, then Vc)
    float* ps   = kv + 128 * CK;       // 64*132 (probs, fp32)
    float* redm = ps + 64 * CS;        // 64*4
    float* reds = redm + 256;          // 64*4
    float* impb = reds + 256;          // 64

    int g = blockIdx.x, h = blockIdx.y, b = blockIdx.z;
    int tid = threadIdx.x, lane = tid & 31, w = tid >> 5;
    int grp = lane >> 2, t4 = lane & 3;
    int wm = w & 1, wn = w >> 1;
    int qbase = g * 64;

    for (int i = tid; i < 1024; i += 256) {
        int r = i >> 4, d4 = (i & 15) * 4;
        float4 v = *(const float4*)(d_Q + (size_t)(b * SEQ + qbase + r) * 512 + h * 64 + d4);
        *(float4*)(&qs[r * CQ + d4]) = v;                 // raw
    }
    int cbase = ((b * NH + h) * NC) * HD;
    for (int i = tid; i < 2048; i += 256) {
        int r = i >> 4, d4 = (i & 15) * 4;
        float4 v = *(const float4*)(d_KC + cbase + r * 64 + d4);
        *(float4*)(&kv[r * CK + d4]) = v;                 // raw
    }
    __syncthreads();

    // ---- QK^T, 3xTF32 ----
    float s[2][4][4];
#pragma unroll
    for (int mt = 0; mt < 2; mt++)
#pragma unroll
        for (int nt = 0; nt < 4; nt++)
#pragma unroll
            for (int r = 0; r < 4; r++) s[mt][nt][r] = 0.f;
#pragma unroll
    for (int ks = 0; ks < 8; ks++) {
        int kk = ks * 8;
        uint32_t ah[2][4], al[2][4], bh[4][2], bl[4][2];
#pragma unroll
        for (int mt = 0; mt < 2; mt++) {
            int row = wm * 32 + mt * 16 + grp;
            split_tf32(qs[row * CQ + kk + t4],           ah[mt][0], al[mt][0]);
            split_tf32(qs[(row + 8) * CQ + kk + t4],     ah[mt][1], al[mt][1]);
            split_tf32(qs[row * CQ + kk + t4 + 4],       ah[mt][2], al[mt][2]);
            split_tf32(qs[(row + 8) * CQ + kk + t4 + 4], ah[mt][3], al[mt][3]);
        }
#pragma unroll
        for (int nt = 0; nt < 4; nt++) {
            int key = wn * 32 + nt * 8 + grp;
            split_tf32(kv[key * CK + kk + t4],     bh[nt][0], bl[nt][0]);
            split_tf32(kv[key * CK + kk + t4 + 4], bh[nt][1], bl[nt][1]);
        }
#pragma unroll
        for (int mt = 0; mt < 2; mt++)
#pragma unroll
            for (int nt = 0; nt < 4; nt++) {
                mma_tf32(s[mt][nt], ah[mt], bl[nt]);   // small terms first
                mma_tf32(s[mt][nt], al[mt], bh[nt]);
                mma_tf32(s[mt][nt], ah[mt], bh[nt]);
            }
    }

    // mask + scale; nvalid per row
    int nval[2][2];
#pragma unroll
    for (int mt = 0; mt < 2; mt++)
#pragma unroll
        for (int hf = 0; hf < 2; hf++) {
            int pos = qbase + wm * 32 + mt * 16 + grp + hf * 8;
            nval[mt][hf] = (pos >= 31) ? ((pos - 31) >> 5) + 1 : 0;
        }
#pragma unroll
    for (int mt = 0; mt < 2; mt++)
#pragma unroll
        for (int nt = 0; nt < 4; nt++)
#pragma unroll
            for (int r = 0; r < 4; r++) {
                int c = wn * 32 + nt * 8 + 2 * t4 + (r & 1);
                bool valid = c < nval[mt][r >> 1];
                s[mt][nt][r] = valid ? s[mt][nt][r] * 0.125f : -1e30f;
            }

    // warp row max (32 cols), cross-warp via redm
#pragma unroll
    for (int mt = 0; mt < 2; mt++)
#pragma unroll
        for (int hf = 0; hf < 2; hf++) {
            float rm = -1e30f;
#pragma unroll
            for (int nt = 0; nt < 4; nt++)
                rm = fmaxf(rm, fmaxf(s[mt][nt][2 * hf], s[mt][nt][2 * hf + 1]));
            rm = fmaxf(rm, __shfl_xor_sync(0xffffffffu, rm, 1));
            rm = fmaxf(rm, __shfl_xor_sync(0xffffffffu, rm, 2));
            if (t4 == 0)
                redm[(wm * 32 + mt * 16 + grp + hf * 8) * 4 + wn] = rm;
        }
    __syncthreads();

    // overwrite kv with Vc (QK done); exp + partial row sums
    for (int i = tid; i < 2048; i += 256) {
        int r = i >> 4, d4 = (i & 15) * 4;
        float4 v = *(const float4*)(d_VC + cbase + r * 64 + d4);
        *(float4*)(&kv[r * CK + d4]) = v;                 // raw
    }
#pragma unroll
    for (int mt = 0; mt < 2; mt++)
#pragma unroll
        for (int hf = 0; hf < 2; hf++) {
            int row = wm * 32 + mt * 16 + grp + hf * 8;
            float gmax = fmaxf(fmaxf(redm[row * 4 + 0], redm[row * 4 + 1]),
                               fmaxf(redm[row * 4 + 2], redm[row * 4 + 3]));
            float rs = 0.f;
#pragma unroll
            for (int nt = 0; nt < 4; nt++) {
                float e0 = __expf(s[mt][nt][2 * hf]     - gmax);
                float e1 = __expf(s[mt][nt][2 * hf + 1] - gmax);
                s[mt][nt][2 * hf] = e0;
                s[mt][nt][2 * hf + 1] = e1;
                rs += e0 + e1;
            }
            rs += __shfl_xor_sync(0xffffffffu, rs, 1);
            rs += __shfl_xor_sync(0xffffffffu, rs, 2);
            if (t4 == 0) reds[row * 4 + wn] = rs;
        }
    __syncthreads();

    // normalize, store P (fp32) to ps
#pragma unroll
    for (int mt = 0; mt < 2; mt++)
#pragma unroll
        for (int hf = 0; hf < 2; hf++) {
            int row = wm * 32 + mt * 16 + grp + hf * 8;
            float tot = reds[row * 4 + 0] + reds[row * 4 + 1] +
                        reds[row * 4 + 2] + reds[row * 4 + 3];
            float inv = (nval[mt][hf] > 0) ? 1.f / tot : 0.f;
#pragma unroll
            for (int nt = 0; nt < 4; nt++) {
                int col = wn * 32 + nt * 8 + 2 * t4;
                ps[row * CS + col]     = s[mt][nt][2 * hf]     * inv;
                ps[row * CS + col + 1] = s[mt][nt][2 * hf + 1] * inv;
            }
        }
    __syncthreads();

    // ---- P * Vc (single tf32) ----
    float o[2][2][4];
#pragma unroll
    for (int mt = 0; mt < 2; mt++)
#pragma unroll
        for (int nt = 0; nt < 2; nt++)
#pragma unroll
            for (int r = 0; r < 4; r++) o[mt][nt][r] = 0.f;
#pragma unroll
    for (int ks = 0; ks < 16; ks++) {
        int kk = ks * 8;
        uint32_t af[2][4], bf[2][2];
#pragma unroll
        for (int mt = 0; mt < 2; mt++) {
            int row = wm * 32 + mt * 16 + grp;
            af[mt][0] = U(ftf(ps[row * CS + kk + t4]));
            af[mt][1] = U(ftf(ps[(row + 8) * CS + kk + t4]));
            af[mt][2] = U(ftf(ps[row * CS + kk + t4 + 4]));
            af[mt][3] = U(ftf(ps[(row + 8) * CS + kk + t4 + 4]));
        }
#pragma unroll
        for (int nt = 0; nt < 2; nt++) {
            int dcol = wn * 16 + nt * 8 + grp;
            bf[nt][0] = U(ftf(kv[(kk + t4) * CK + dcol]));
            bf[nt][1] = U(ftf(kv[(kk + t4 + 4) * CK + dcol]));
        }
#pragma unroll
        for (int mt = 0; mt < 2; mt++)
#pragma unroll
            for (int nt = 0; nt < 2; nt++)
                mma_tf32(o[mt][nt], af[mt], bf[nt]);
    }

    // write d_O = g0 * out_c
#pragma unroll
    for (int mt = 0; mt < 2; mt++)
#pragma unroll
        for (int hf = 0; hf < 2; hf++) {
            int qp = qbase + wm * 32 + mt * 16 + grp + hf * 8;
            float g0 = d_G[(b * SEQ + qp) * 3 + 0];
#pragma unroll
            for (int nt = 0; nt < 2; nt++) {
                int dcol = wn * 16 + nt * 8 + 2 * t4;
                size_t ob = (size_t)(b * SEQ + qp) * 512 + h * 64 + dcol;
                *(float2*)(d_O + ob) = make_float2(o[mt][nt][2 * hf] * g0,
                                                   o[mt][nt][2 * hf + 1] * g0);
            }
        }
    __syncthreads();

    // importance per selection block
    if (tid < 64) {
        float v = 0.f;
        for (int q = 0; q < 64; q++)
            v += ps[q * CS + 2 * tid] + ps[q * CS + 2 * tid + 1];
        impb[tid] = v;
    }
    __syncthreads();
    if (w == 0) {
        int j0 = lane, j1 = lane + 32;
        float v0 = (j0 <= g) ? impb[j0] + (j0 == g ? 1e9f : 0.f) : -1e30f;
        float v1 = (j1 <= g) ? impb[j1] + (j1 == g ? 1e9f : 0.f) : -1e30f;
        int selbase = ((b * NH + h) * NS + g) * TOPK;
        for (int r = 0; r < TOPK; r++) {
            float bv; int bi;
            if (v0 >= v1) { bv = v0; bi = j0; } else { bv = v1; bi = j1; }
#pragma unroll
            for (int o2 = 16; o2; o2 >>= 1) {
                float ov = __shfl_xor_sync(0xffffffffu, bv, o2);
                int   oi = __shfl_xor_sync(0xffffffffu, bi, o2);
                if (ov > bv || (ov == bv && oi < bi)) { bv = ov; bi = oi; }
            }
            if (lane == 0) d_SEL[selbase + r] = bi;
            if (bi == j0) v0 = -3e30f;
            if (bi == j1) v1 = -3e30f;
        }
    }
}

// ---------------- selection / window flash attention (tf32 mma + prefetch) -
#define PK 68
#define PV 72
__global__ __launch_bounds__(256) void sel_win_kernel(int mode)
{
    extern __shared__ float sm[];
    float* qs   = sm;                 // 64*68
    float* Ks   = qs + 64 * PK;       // 64*68
    float* Vs   = Ks + 64 * PK;       // 64*72
    float* ps   = Vs + 64 * PV;       // 64*68
    float* redm = ps + 64 * PK;       // 64*4
    float* reds = redm + 64 * 4;      // 64*4

    int g = blockIdx.x, hh = blockIdx.y, b = blockIdx.z;
    int tid = threadIdx.x, lane = tid & 31, w = tid >> 5;
    int grp = lane >> 2, t4 = lane & 3;
    int wm = w & 1, wn = w >> 1;
    int qbase = g * 64;

    for (int i = tid; i < 1024; i += 256) {
        int r = i >> 4, d4 = (i & 15) * 4;
        float4 v = *(const float4*)(d_Q + (size_t)(b * SEQ + qbase + r) * 512 + hh * 64 + d4);
        *(float4*)(&qs[r * PK + d4]) = ftf4(v);
    }

    int selbase = ((b * NH + hh) * NS + g) * TOPK;
    int kblist[16];
    int nkb = 0;
    if (mode) {
        int st = (g > 8) ? g - 8 : 0;
        for (int kb = st; kb <= g; kb++) kblist[nkb++] = kb;
    } else {
        for (int it = 0; it < TOPK; it++) kblist[nkb++] = d_SEL[selbase + it];
    }

    float o[2][2][4];
#pragma unroll
    for (int mt = 0; mt < 2; mt++)
#pragma unroll
        for (int nt = 0; nt < 2; nt++)
#pragma unroll
            for (int r = 0; r < 4; r++) o[mt][nt][r] = 0.f;
    float mst[2][2], lst[2][2];
#pragma unroll
    for (int mt = 0; mt < 2; mt++)
#pragma unroll
        for (int hf = 0; hf < 2; hf++) { mst[mt][hf] = -1e30f; lst[mt][hf] = 0.f; }

    float4 kreg[4], vreg[4];
    int pr = tid >> 4, pd4 = (tid & 15) * 4;
    {
        size_t kbase = (size_t)(b * SEQ + kblist[0] * 64) * 512 + hh * 64;
#pragma unroll
        for (int j = 0; j < 4; j++) {
            kreg[j] = *(const float4*)(d_K + kbase + (size_t)(pr + j * 16) * 512 + pd4);
            vreg[j] = *(const float4*)(d_V + kbase + (size_t)(pr + j * 16) * 512 + pd4);
        }
    }
    __syncthreads();

    for (int t = 0; t < nkb; t++) {
        int kb = kblist[t];
#pragma unroll
        for (int j = 0; j < 4; j++) {
            int r = pr + j * 16;
            *(float4*)(&Ks[r * PK + pd4]) = ftf4(kreg[j]);
            *(float4*)(&Vs[r * PV + pd4]) = ftf4(vreg[j]);
        }
        __syncthreads();
        if (t + 1 < nkb) {
            size_t kbase = (size_t)(b * SEQ + kblist[t + 1] * 64) * 512 + hh * 64;
#pragma unroll
            for (int j = 0; j < 4; j++) {
                kreg[j] = *(const float4*)(d_K + kbase + (size_t)(pr + j * 16) * 512 + pd4);
                vreg[j] = *(const float4*)(d_V + kbase + (size_t)(pr + j * 16) * 512 + pd4);
            }
        }

        float s[2][2][4];
#pragma unroll
        for (int mt = 0; mt < 2; mt++)
#pragma unroll
            for (int nt = 0; nt < 2; nt++)
#pragma unroll
                for (int r = 0; r < 4; r++) s[mt][nt][r] = 0.f;
#pragma unroll
        for (int ks = 0; ks < 8; ks++) {
            int kk = ks * 8;
            uint32_t af[2][4], bf[2][2];
#pragma unroll
            for (int mt = 0; mt < 2; mt++) {
                int row = wm * 32 + mt * 16 + grp;
                af[mt][0] = U(qs[row * PK + kk + t4]);
                af[mt][1] = U(qs[(row + 8) * PK + kk + t4]);
                af[mt][2] = U(qs[row * PK + kk + t4 + 4]);
                af[mt][3] = U(qs[(row + 8) * PK + kk + t4 + 4]);
            }
#pragma unroll
            for (int nt = 0; nt < 2; nt++) {
                int key = wn * 16 + nt * 8 + grp;
                bf[nt][0] = U(Ks[key * PK + kk + t4]);
                bf[nt][1] = U(Ks[key * PK + kk + t4 + 4]);
            }
#pragma unroll
            for (int mt = 0; mt < 2; mt++)
#pragma unroll
                for (int nt = 0; nt < 2; nt++)
                    mma_tf32(s[mt][nt], af[mt], bf[nt]);
        }

#pragma unroll
        for (int mt = 0; mt < 2; mt++)
#pragma unroll
            for (int nt = 0; nt < 2; nt++)
#pragma unroll
                for (int r = 0; r < 4; r++) {
                    int qp = qbase + wm * 32 + mt * 16 + grp + (r >> 1) * 8;
                    int kp = kb * 64 + wn * 16 + nt * 8 + 2 * t4 + (r & 1);
                    bool valid = (kp <= qp) && (!mode || (kp + 512 > qp));
                    s[mt][nt][r] = valid ? s[mt][nt][r] * 0.125f : -1e30f;
                }

#pragma unroll
        for (int mt = 0; mt < 2; mt++)
#pragma unroll
            for (int hf = 0; hf < 2; hf++) {
                float rm = fmaxf(fmaxf(s[mt][0][2 * hf], s[mt][0][2 * hf + 1]),
                                 fmaxf(s[mt][1][2 * hf], s[mt][1][2 * hf + 1]));
                rm = fmaxf(rm, __shfl_xor_sync(0xffffffffu, rm, 1));
                rm = fmaxf(rm, __shfl_xor_sync(0xffffffffu, rm, 2));
                if (t4 == 0)
                    redm[(wm * 32 + mt * 16 + grp + hf * 8) * 4 + wn] = rm;
            }
        __syncthreads();

        float corr[2][2], mnew[2][2];
#pragma unroll
        for (int mt = 0; mt < 2; mt++)
#pragma unroll
            for (int hf = 0; hf < 2; hf++) {
                int row = wm * 32 + mt * 16 + grp + hf * 8;
                float gmax = fmaxf(fmaxf(redm[row * 4 + 0], redm[row * 4 + 1]),
                                   fmaxf(redm[row * 4 + 2], redm[row * 4 + 3]));
                float mn = fmaxf(mst[mt][hf], gmax);
                mnew[mt][hf] = mn;
                corr[mt][hf] = __expf(mst[mt][hf] - mn);
            }

#pragma unroll
        for (int mt = 0; mt < 2; mt++)
#pragma unroll
            for (int hf = 0; hf < 2; hf++) {
                int rowl = wm * 32 + mt * 16 + grp + hf * 8;
                float mn = mnew[mt][hf];
                float rs = 0.f;
#pragma unroll
                for (int nt = 0; nt < 2; nt++) {
                    float p0 = __expf(s[mt][nt][2 * hf]     - mn);
                    float p1 = __expf(s[mt][nt][2 * hf + 1] - mn);
                    rs += p0 + p1;
                    int col = wn * 16 + nt * 8 + 2 * t4;
                    ps[rowl * PK + col]     = ftf(p0);
                    ps[rowl * PK + col + 1] = ftf(p1);
                }
                rs += __shfl_xor_sync(0xffffffffu, rs, 1);
                rs += __shfl_xor_sync(0xffffffffu, rs, 2);
                if (t4 == 0) reds[rowl * 4 + wn] = rs;
            }
        __syncthreads();

#pragma unroll
        for (int mt = 0; mt < 2; mt++)
#pragma unroll
            for (int hf = 0; hf < 2; hf++) {
                int row = wm * 32 + mt * 16 + grp + hf * 8;
                float ls = reds[row * 4 + 0] + reds[row * 4 + 1] +
                           reds[row * 4 + 2] + reds[row * 4 + 3];
                float cr = corr[mt][hf];
                lst[mt][hf] = lst[mt][hf] * cr + ls;
                mst[mt][hf] = mnew[mt][hf];
#pragma unroll
                for (int nt = 0; nt < 2; nt++) {
                    o[mt][nt][2 * hf]     *= cr;
                    o[mt][nt][2 * hf + 1] *= cr;
                }
            }

#pragma unroll
        for (int ks = 0; ks < 8; ks++) {
            int kk = ks * 8;
            uint32_t af[2][4], bf[2][2];
#pragma unroll
            for (int mt = 0; mt < 2; mt++) {
                int row = wm * 32 + mt * 16 + grp;
                af[mt][0] = U(ps[row * PK + kk + t4]);
                af[mt][1] = U(ps[(row + 8) * PK + kk + t4]);
                af[mt][2] = U(ps[row * PK + kk + t4 + 4]);
                af[mt][3] = U(ps[(row + 8) * PK + kk + t4 + 4]);
            }
#pragma unroll
            for (int nt = 0; nt < 2; nt++) {
                int dcol = wn * 16 + nt * 8 + grp;
                bf[nt][0] = U(Vs[(kk + t4) * PV + dcol]);
                bf[nt][1] = U(Vs[(kk + t4 + 4) * PV + dcol]);
            }
#pragma unroll
            for (int mt = 0; mt < 2; mt++)
#pragma unroll
                for (int nt = 0; nt < 2; nt++)
                    mma_tf32(o[mt][nt], af[mt], bf[nt]);
        }
        __syncthreads();
    }

#pragma unroll
    for (int mt = 0; mt < 2; mt++)
#pragma unroll
        for (int hf = 0; hf < 2; hf++) {
            int qp = qbase + wm * 32 + mt * 16 + grp + hf * 8;
            float gv = d_G[(b * SEQ + qp) * 3 + (mode ? 2 : 1)];
            float inv = gv / lst[mt][hf];
#pragma unroll
            for (int nt = 0; nt < 2; nt++) {
                int dcol = wn * 16 + nt * 8 + 2 * t4;
                size_t ob = (size_t)(b * SEQ + qp) * 512 + hh * 64 + dcol;
                float2 cur = *(float2*)(d_O + ob);
                cur.x += o[mt][nt][2 * hf]     * inv;
                cur.y += o[mt][nt][2 * hf + 1] * inv;
                *(float2*)(d_O + ob) = cur;
            }
        }
}

// ---------------------------------------------------------------------------
extern "C" void kernel_launch(void* const* d_in, const int* in_sizes, int n_in,
                              void* d_out, int out_size)
{
    const float* x  = (const float*)d_in[0];
    const float* Wq = (const float*)d_in[1];
    const float* Wk = (const float*)d_in[2];
    const float* Wv = (const float*)d_in[3];
    const float* Wo = (const float*)d_in[4];
    const float* Wg = (const float*)d_in[5];
    float* y = (float*)d_out;

    cudaFuncSetAttribute(cmp_attn_mma,
                         cudaFuncAttributeMaxDynamicSharedMemorySize, 90368);
    cudaFuncSetAttribute(sel_win_kernel,
                         cudaFuncAttributeMaxDynamicSharedMemorySize, 72704);

    gemm512_tc<<<dim3(8, 64, 3), 256>>>(x, Wq, Wk, Wv, nullptr, 0);
    gate_kernel<<<NROWS, 128>>>(x, Wg);
    compress_kernel<<<(BATCH * NH * NC * HD) / 256, 256>>>();
    cmp_attn_mma<<<dim3(64, 8, 2), 256, 90368>>>();
    sel_win_kernel<<<dim3(64, 8, 2), 256, 72704>>>(0);
    sel_win_kernel<<<dim3(64, 8, 2), 256, 72704>>>(1);
    gemm512_tc<<<dim3(8, 64, 1), 256>>>(nullptr, Wo, nullptr, nullptr, y, 3);
}

// round 6
// speedup vs baseline: 5.8729x; 1.0082x over previous
#include <cuda_runtime.h>
#include <math.h>
#include <stdint.h>

#define BATCH   2
#define SEQ     4096
#define DMODEL  512
#define NH      8
#define HD      64
#define NC      128
#define NS      64
#define TOPK    16
#define NROWS   (BATCH*SEQ)

// ---------------- scratch ----------------
__device__ float d_Q[NROWS*DMODEL];
__device__ float d_K[NROWS*DMODEL];
__device__ float d_V[NROWS*DMODEL];
__device__ float d_O[NROWS*DMODEL];
__device__ float d_KC[BATCH*NH*NC*HD];
__device__ float d_VC[BATCH*NH*NC*HD];
__device__ float d_G[NROWS*3];
__device__ int   d_SEL[BATCH*NH*NS*TOPK];

// ---------------- tf32 helpers ----------------
__device__ __forceinline__ float ftf(float x) {
    uint32_t u;
    asm("cvt.rna.tf32.f32 %0, %1;" : "=r"(u) : "f"(x));
    return __uint_as_float(u);
}
__device__ __forceinline__ float4 ftf4(float4 v) {
    return make_float4(ftf(v.x), ftf(v.y), ftf(v.z), ftf(v.w));
}
__device__ __forceinline__ void mma_tf32(float* c, const uint32_t* a, const uint32_t* b) {
    asm volatile(
        "mma.sync.aligned.m16n8k8.row.col.f32.tf32.tf32.f32 "
        "{%0,%1,%2,%3},{%4,%5,%6,%7},{%8,%9},{%0,%1,%2,%3};\n"
        : "+f"(c[0]), "+f"(c[1]), "+f"(c[2]), "+f"(c[3])
        : "r"(a[0]), "r"(a[1]), "r"(a[2]), "r"(a[3]), "r"(b[0]), "r"(b[1]));
}
__device__ __forceinline__ void split_tf32(float x, uint32_t& hi, uint32_t& lo) {
    float h = ftf(x);
    hi = __float_as_uint(h);
    lo = __float_as_uint(ftf(x - h));
}
#define U(x) __float_as_uint(x)

// ---------------- tf32 tensor-core GEMM with register prefetch ------------
#define GPA 20
#define GPB 72
__global__ __launch_bounds__(256) void gemm512_tc(const float* __restrict__ Aext,
    const float* __restrict__ B0, const float* __restrict__ B1,
    const float* __restrict__ B2, float* __restrict__ Cext, int modeBase)
{
    int mode = modeBase + blockIdx.z;
    const float* A  = (mode == 3) ? d_O : Aext;
    const float* Bm = (mode == 1) ? B1 : (mode == 2) ? B2 : B0;
    float* C = (mode == 0) ? d_Q : (mode == 1) ? d_K : (mode == 2) ? d_V : Cext;

    __shared__ float As[128 * GPA];
    __shared__ float Bs[16 * GPB];

    int tid = threadIdx.x, lane = tid & 31, w = tid >> 5;
    int grp = lane >> 2, t4 = lane & 3;
    int wm = w & 3, wn = w >> 2;
    int m0 = blockIdx.y * 128, n0 = blockIdx.x * 64;

    // load indices
    int ar0 = tid >> 2,        ak0 = (tid & 3) * 4;          // A chunk 0
    int ar1 = (tid + 256) >> 2, ak1 = ((tid + 256) & 3) * 4; // A chunk 1
    int brr = tid >> 4,        bc4 = (tid & 15) * 4;         // B chunk

    float acc[2][4][4];
#pragma unroll
    for (int mt = 0; mt < 2; mt++)
#pragma unroll
        for (int nt = 0; nt < 4; nt++)
#pragma unroll
            for (int r = 0; r < 4; r++) acc[mt][nt][r] = 0.f;

    // preload k0 = 0
    float4 apre0 = *(const float4*)(A + (size_t)(m0 + ar0) * 512 + ak0);
    float4 apre1 = *(const float4*)(A + (size_t)(m0 + ar1) * 512 + ak1);
    float4 bpre  = *(const float4*)(Bm + (size_t)brr * 512 + n0 + bc4);

    for (int k0 = 0; k0 < 512; k0 += 16) {
        *(float4*)(&As[ar0 * GPA + ak0]) = ftf4(apre0);
        *(float4*)(&As[ar1 * GPA + ak1]) = ftf4(apre1);
        *(float4*)(&Bs[brr * GPB + bc4]) = ftf4(bpre);
        __syncthreads();
        if (k0 + 16 < 512) {
            apre0 = *(const float4*)(A + (size_t)(m0 + ar0) * 512 + k0 + 16 + ak0);
            apre1 = *(const float4*)(A + (size_t)(m0 + ar1) * 512 + k0 + 16 + ak1);
            bpre  = *(const float4*)(Bm + (size_t)(k0 + 16 + brr) * 512 + n0 + bc4);
        }
#pragma unroll
        for (int ks = 0; ks < 2; ks++) {
            int kb = ks * 8;
            uint32_t af[2][4], bf[4][2];
#pragma unroll
            for (int mt = 0; mt < 2; mt++) {
                int row = wm * 32 + mt * 16 + grp;
                af[mt][0] = U(As[row * GPA + kb + t4]);
                af[mt][1] = U(As[(row + 8) * GPA + kb + t4]);
                af[mt][2] = U(As[row * GPA + kb + t4 + 4]);
                af[mt][3] = U(As[(row + 8) * GPA + kb + t4 + 4]);
            }
#pragma unroll
            for (int nt = 0; nt < 4; nt++) {
                int col = wn * 32 + nt * 8 + grp;
                bf[nt][0] = U(Bs[(kb + t4) * GPB + col]);
                bf[nt][1] = U(Bs[(kb + t4 + 4) * GPB + col]);
            }
#pragma unroll
            for (int mt = 0; mt < 2; mt++)
#pragma unroll
                for (int nt = 0; nt < 4; nt++)
                    mma_tf32(acc[mt][nt], af[mt], bf[nt]);
        }
        __syncthreads();
    }
#pragma unroll
    for (int mt = 0; mt < 2; mt++)
#pragma unroll
        for (int nt = 0; nt < 4; nt++) {
            int row = m0 + wm * 32 + mt * 16 + grp;
            int col = n0 + wn * 32 + nt * 8 + 2 * t4;
            *(float2*)(C + (size_t)row * 512 + col) =
                make_float2(acc[mt][nt][0], acc[mt][nt][1]);
            *(float2*)(C + (size_t)(row + 8) * 512 + col) =
                make_float2(acc[mt][nt][2], acc[mt][nt][3]);
        }
}

// ---------------- gate ----------------
__global__ __launch_bounds__(128) void gate_kernel(const float* __restrict__ x,
                                                   const float* __restrict__ Wg)
{
    int row = blockIdx.x;
    int tid = threadIdx.x, lane = tid & 31, w = tid >> 5;
    float p0 = 0, p1 = 0, p2 = 0;
    for (int d = tid; d < 512; d += 128) {
        float xv = x[(size_t)row * 512 + d];
        p0 += xv * Wg[d * 3 + 0];
        p1 += xv * Wg[d * 3 + 1];
        p2 += xv * Wg[d * 3 + 2];
    }
#pragma unroll
    for (int o = 16; o; o >>= 1) {
        p0 += __shfl_xor_sync(0xffffffffu, p0, o);
        p1 += __shfl_xor_sync(0xffffffffu, p1, o);
        p2 += __shfl_xor_sync(0xffffffffu, p2, o);
    }
    __shared__ float red[3][4];
    if (lane == 0) { red[0][w] = p0; red[1][w] = p1; red[2][w] = p2; }
    __syncthreads();
    if (tid < 3) {
        float v = red[tid][0] + red[tid][1] + red[tid][2] + red[tid][3];
        d_G[row * 3 + tid] = 1.f / (1.f + expf(-v));
    }
}

// ---------------- compressed K/V means ----------------
__global__ __launch_bounds__(256) void compress_kernel()
{
    int idx = blockIdx.x * 256 + threadIdx.x;
    int d = idx & 63, n = (idx >> 6) & 127, h = (idx >> 13) & 7, b = idx >> 16;
    const float* kp = d_K + (size_t)(b * SEQ + n * 32) * 512 + h * 64 + d;
    const float* vp = d_V + (size_t)(b * SEQ + n * 32) * 512 + h * 64 + d;
    float ks = 0, vs = 0;
#pragma unroll
    for (int r = 0; r < 32; r++) { ks += kp[r * 512]; vs += vp[r * 512]; }
    d_KC[idx] = ks * (1.f / 32.f);
    d_VC[idx] = vs * (1.f / 32.f);
}

// ---------------- compressed attention + top-k (3xTF32 QK) ----------------
#define CQ 68
#define CK 72
#define CS 132
__global__ __launch_bounds__(256) void cmp_attn_mma()
{
    extern __shared__ float sm[];
    float* qs   = sm;                  // 64*68  (raw fp32 Q)
    float* kv   = qs + 64 * CQ;        // 128*72 (raw fp32 Kc, then Vc)
    float* ps   = kv + 128 * CK;       // 64*132 (probs, fp32)
    float* redm = ps + 64 * CS;        // 64*4
    float* reds = redm + 256;          // 64*4
    float* impb = reds + 256;          // 64

    int g = blockIdx.x, h = blockIdx.y, b = blockIdx.z;
    int tid = threadIdx.x, lane = tid & 31, w = tid >> 5;
    int grp = lane >> 2, t4 = lane & 3;
    int wm = w & 1, wn = w >> 1;
    int qbase = g * 64;

    for (int i = tid; i < 1024; i += 256) {
        int r = i >> 4, d4 = (i & 15) * 4;
        float4 v = *(const float4*)(d_Q + (size_t)(b * SEQ + qbase + r) * 512 + h * 64 + d4);
        *(float4*)(&qs[r * CQ + d4]) = v;
    }
    int cbase = ((b * NH + h) * NC) * HD;
    for (int i = tid; i < 2048; i += 256) {
        int r = i >> 4, d4 = (i & 15) * 4;
        float4 v = *(const float4*)(d_KC + cbase + r * 64 + d4);
        *(float4*)(&kv[r * CK + d4]) = v;
    }
    __syncthreads();

    float s[2][4][4];
#pragma unroll
    for (int mt = 0; mt < 2; mt++)
#pragma unroll
        for (int nt = 0; nt < 4; nt++)
#pragma unroll
            for (int r = 0; r < 4; r++) s[mt][nt][r] = 0.f;
#pragma unroll
    for (int ks = 0; ks < 8; ks++) {
        int kk = ks * 8;
        uint32_t ah[2][4], al[2][4], bh[4][2], bl[4][2];
#pragma unroll
        for (int mt = 0; mt < 2; mt++) {
            int row = wm * 32 + mt * 16 + grp;
            split_tf32(qs[row * CQ + kk + t4],           ah[mt][0], al[mt][0]);
            split_tf32(qs[(row + 8) * CQ + kk + t4],     ah[mt][1], al[mt][1]);
            split_tf32(qs[row * CQ + kk + t4 + 4],       ah[mt][2], al[mt][2]);
            split_tf32(qs[(row + 8) * CQ + kk + t4 + 4], ah[mt][3], al[mt][3]);
        }
#pragma unroll
        for (int nt = 0; nt < 4; nt++) {
            int key = wn * 32 + nt * 8 + grp;
            split_tf32(kv[key * CK + kk + t4],     bh[nt][0], bl[nt][0]);
            split_tf32(kv[key * CK + kk + t4 + 4], bh[nt][1], bl[nt][1]);
        }
#pragma unroll
        for (int mt = 0; mt < 2; mt++)
#pragma unroll
            for (int nt = 0; nt < 4; nt++) {
                mma_tf32(s[mt][nt], ah[mt], bl[nt]);
                mma_tf32(s[mt][nt], al[mt], bh[nt]);
                mma_tf32(s[mt][nt], ah[mt], bh[nt]);
            }
    }

    int nval[2][2];
#pragma unroll
    for (int mt = 0; mt < 2; mt++)
#pragma unroll
        for (int hf = 0; hf < 2; hf++) {
            int pos = qbase + wm * 32 + mt * 16 + grp + hf * 8;
            nval[mt][hf] = (pos >= 31) ? ((pos - 31) >> 5) + 1 : 0;
        }
#pragma unroll
    for (int mt = 0; mt < 2; mt++)
#pragma unroll
        for (int nt = 0; nt < 4; nt++)
#pragma unroll
            for (int r = 0; r < 4; r++) {
                int c = wn * 32 + nt * 8 + 2 * t4 + (r & 1);
                bool valid = c < nval[mt][r >> 1];
                s[mt][nt][r] = valid ? s[mt][nt][r] * 0.125f : -1e30f;
            }

#pragma unroll
    for (int mt = 0; mt < 2; mt++)
#pragma unroll
        for (int hf = 0; hf < 2; hf++) {
            float rm = -1e30f;
#pragma unroll
            for (int nt = 0; nt < 4; nt++)
                rm = fmaxf(rm, fmaxf(s[mt][nt][2 * hf], s[mt][nt][2 * hf + 1]));
            rm = fmaxf(rm, __shfl_xor_sync(0xffffffffu, rm, 1));
            rm = fmaxf(rm, __shfl_xor_sync(0xffffffffu, rm, 2));
            if (t4 == 0)
                redm[(wm * 32 + mt * 16 + grp + hf * 8) * 4 + wn] = rm;
        }
    __syncthreads();

    for (int i = tid; i < 2048; i += 256) {
        int r = i >> 4, d4 = (i & 15) * 4;
        float4 v = *(const float4*)(d_VC + cbase + r * 64 + d4);
        *(float4*)(&kv[r * CK + d4]) = v;
    }
#pragma unroll
    for (int mt = 0; mt < 2; mt++)
#pragma unroll
        for (int hf = 0; hf < 2; hf++) {
            int row = wm * 32 + mt * 16 + grp + hf * 8;
            float gmax = fmaxf(fmaxf(redm[row * 4 + 0], redm[row * 4 + 1]),
                               fmaxf(redm[row * 4 + 2], redm[row * 4 + 3]));
            float rs = 0.f;
#pragma unroll
            for (int nt = 0; nt < 4; nt++) {
                float e0 = __expf(s[mt][nt][2 * hf]     - gmax);
                float e1 = __expf(s[mt][nt][2 * hf + 1] - gmax);
                s[mt][nt][2 * hf] = e0;
                s[mt][nt][2 * hf + 1] = e1;
                rs += e0 + e1;
            }
            rs += __shfl_xor_sync(0xffffffffu, rs, 1);
            rs += __shfl_xor_sync(0xffffffffu, rs, 2);
            if (t4 == 0) reds[row * 4 + wn] = rs;
        }
    __syncthreads();

#pragma unroll
    for (int mt = 0; mt < 2; mt++)
#pragma unroll
        for (int hf = 0; hf < 2; hf++) {
            int row = wm * 32 + mt * 16 + grp + hf * 8;
            float tot = reds[row * 4 + 0] + reds[row * 4 + 1] +
                        reds[row * 4 + 2] + reds[row * 4 + 3];
            float inv = (nval[mt][hf] > 0) ? 1.f / tot : 0.f;
#pragma unroll
            for (int nt = 0; nt < 4; nt++) {
                int col = wn * 32 + nt * 8 + 2 * t4;
                ps[row * CS + col]     = s[mt][nt][2 * hf]     * inv;
                ps[row * CS + col + 1] = s[mt][nt][2 * hf + 1] * inv;
            }
        }
    __syncthreads();

    float o[2][2][4];
#pragma unroll
    for (int mt = 0; mt < 2; mt++)
#pragma unroll
        for (int nt = 0; nt < 2; nt++)
#pragma unroll
            for (int r = 0; r < 4; r++) o[mt][nt][r] = 0.f;
#pragma unroll
    for (int ks = 0; ks < 16; ks++) {
        int kk = ks * 8;
        uint32_t af[2][4], bf[2][2];
#pragma unroll
        for (int mt = 0; mt < 2; mt++) {
            int row = wm * 32 + mt * 16 + grp;
            af[mt][0] = U(ftf(ps[row * CS + kk + t4]));
            af[mt][1] = U(ftf(ps[(row + 8) * CS + kk + t4]));
            af[mt][2] = U(ftf(ps[row * CS + kk + t4 + 4]));
            af[mt][3] = U(ftf(ps[(row + 8) * CS + kk + t4 + 4]));
        }
#pragma unroll
        for (int nt = 0; nt < 2; nt++) {
            int dcol = wn * 16 + nt * 8 + grp;
            bf[nt][0] = U(ftf(kv[(kk + t4) * CK + dcol]));
            bf[nt][1] = U(ftf(kv[(kk + t4 + 4) * CK + dcol]));
        }
#pragma unroll
        for (int mt = 0; mt < 2; mt++)
#pragma unroll
            for (int nt = 0; nt < 2; nt++)
                mma_tf32(o[mt][nt], af[mt], bf[nt]);
    }

#pragma unroll
    for (int mt = 0; mt < 2; mt++)
#pragma unroll
        for (int hf = 0; hf < 2; hf++) {
            int qp = qbase + wm * 32 + mt * 16 + grp + hf * 8;
            float g0 = d_G[(b * SEQ + qp) * 3 + 0];
#pragma unroll
            for (int nt = 0; nt < 2; nt++) {
                int dcol = wn * 16 + nt * 8 + 2 * t4;
                size_t ob = (size_t)(b * SEQ + qp) * 512 + h * 64 + dcol;
                *(float2*)(d_O + ob) = make_float2(o[mt][nt][2 * hf] * g0,
                                                   o[mt][nt][2 * hf + 1] * g0);
            }
        }
    __syncthreads();

    if (tid < 64) {
        float v = 0.f;
        for (int q = 0; q < 64; q++)
            v += ps[q * CS + 2 * tid] + ps[q * CS + 2 * tid + 1];
        impb[tid] = v;
    }
    __syncthreads();
    if (w == 0) {
        int j0 = lane, j1 = lane + 32;
        float v0 = (j0 <= g) ? impb[j0] + (j0 == g ? 1e9f : 0.f) : -1e30f;
        float v1 = (j1 <= g) ? impb[j1] + (j1 == g ? 1e9f : 0.f) : -1e30f;
        int selbase = ((b * NH + h) * NS + g) * TOPK;
        for (int r = 0; r < TOPK; r++) {
            float bv; int bi;
            if (v0 >= v1) { bv = v0; bi = j0; } else { bv = v1; bi = j1; }
#pragma unroll
            for (int o2 = 16; o2; o2 >>= 1) {
                float ov = __shfl_xor_sync(0xffffffffu, bv, o2);
                int   oi = __shfl_xor_sync(0xffffffffu, bi, o2);
                if (ov > bv || (ov == bv && oi < bi)) { bv = ov; bi = oi; }
            }
            if (lane == 0) d_SEL[selbase + r] = bi;
            if (bi == j0) v0 = -3e30f;
            if (bi == j1) v1 = -3e30f;
        }
    }
}

// ---------------- fused selection + window flash attention -----------------
// One CTA per (g,h,b): runs filtered sel tiles (phase 0) then win tiles
// (phase 1) with independent softmax states; single combined d_O RMW.
#define PK 68
#define PV 72
__global__ __launch_bounds__(256) void selwin_fused()
{
    extern __shared__ float sm[];
    float* qs   = sm;                 // 64*68
    float* Ks   = qs + 64 * PK;       // 64*68
    float* Vs   = Ks + 64 * PK;       // 64*72
    float* ps   = Vs + 64 * PV;       // 64*68
    float* redm = ps + 64 * PK;       // 64*4
    float* reds = redm + 64 * 4;      // 64*4

    int g = blockIdx.x, hh = blockIdx.y, b = blockIdx.z;
    int tid = threadIdx.x, lane = tid & 31, w = tid >> 5;
    int grp = lane >> 2, t4 = lane & 3;
    int wm = w & 1, wn = w >> 1;
    int qbase = g * 64;

    for (int i = tid; i < 1024; i += 256) {
        int r = i >> 4, d4 = (i & 15) * 4;
        float4 v = *(const float4*)(d_Q + (size_t)(b * SEQ + qbase + r) * 512 + hh * 64 + d4);
        *(float4*)(&qs[r * PK + d4]) = ftf4(v);
    }

    // combined tile list: [0, nsel) = selected blocks (filtered kb<=g),
    // [nsel, ntot) = window blocks max(0,g-8)..g
    int selbase = ((b * NH + hh) * NS + g) * TOPK;
    int kblist[25];
    int nsel = 0;
#pragma unroll
    for (int it = 0; it < TOPK; it++) {
        int kb = d_SEL[selbase + it];
        if (kb <= g) kblist[nsel++] = kb;   // drop padded (fully masked) picks
    }
    int ntot = nsel;
    {
        int st = (g > 8) ? g - 8 : 0;
        for (int kb = st; kb <= g; kb++) kblist[ntot++] = kb;
    }

    // gates per owned row
    float gv1[2][2], gv2[2][2];
#pragma unroll
    for (int mt = 0; mt < 2; mt++)
#pragma unroll
        for (int hf = 0; hf < 2; hf++) {
            int qp = qbase + wm * 32 + mt * 16 + grp + hf * 8;
            gv1[mt][hf] = d_G[(b * SEQ + qp) * 3 + 1];
            gv2[mt][hf] = d_G[(b * SEQ + qp) * 3 + 2];
        }

    float out_acc[2][2][4];
    float o[2][2][4];
#pragma unroll
    for (int mt = 0; mt < 2; mt++)
#pragma unroll
        for (int nt = 0; nt < 2; nt++)
#pragma unroll
            for (int r = 0; r < 4; r++) { out_acc[mt][nt][r] = 0.f; o[mt][nt][r] = 0.f; }
    float mst[2][2], lst[2][2];
#pragma unroll
    for (int mt = 0; mt < 2; mt++)
#pragma unroll
        for (int hf = 0; hf < 2; hf++) { mst[mt][hf] = -1e30f; lst[mt][hf] = 0.f; }

    float4 kreg[4], vreg[4];
    int pr = tid >> 4, pd4 = (tid & 15) * 4;
    {
        size_t kbase = (size_t)(b * SEQ + kblist[0] * 64) * 512 + hh * 64;
#pragma unroll
        for (int j = 0; j < 4; j++) {
            kreg[j] = *(const float4*)(d_K + kbase + (size_t)(pr + j * 16) * 512 + pd4);
            vreg[j] = *(const float4*)(d_V + kbase + (size_t)(pr + j * 16) * 512 + pd4);
        }
    }
    __syncthreads();

    for (int t = 0; t < ntot; t++) {
        if (t == nsel) {
            // finalize sel phase into out_acc, reset state for win phase
#pragma unroll
            for (int mt = 0; mt < 2; mt++)
#pragma unroll
                for (int hf = 0; hf < 2; hf++) {
                    float inv = gv1[mt][hf] / lst[mt][hf];
#pragma unroll
                    for (int nt = 0; nt < 2; nt++) {
                        out_acc[mt][nt][2 * hf]     += o[mt][nt][2 * hf]     * inv;
                        out_acc[mt][nt][2 * hf + 1] += o[mt][nt][2 * hf + 1] * inv;
                        o[mt][nt][2 * hf] = 0.f; o[mt][nt][2 * hf + 1] = 0.f;
                    }
                    mst[mt][hf] = -1e30f; lst[mt][hf] = 0.f;
                }
        }
        int kb = kblist[t];
        bool winph = (t >= nsel);

#pragma unroll
        for (int j = 0; j < 4; j++) {
            int r = pr + j * 16;
            *(float4*)(&Ks[r * PK + pd4]) = ftf4(kreg[j]);
            *(float4*)(&Vs[r * PV + pd4]) = ftf4(vreg[j]);
        }
        __syncthreads();
        if (t + 1 < ntot) {
            size_t kbase = (size_t)(b * SEQ + kblist[t + 1] * 64) * 512 + hh * 64;
#pragma unroll
            for (int j = 0; j < 4; j++) {
                kreg[j] = *(const float4*)(d_K + kbase + (size_t)(pr + j * 16) * 512 + pd4);
                vreg[j] = *(const float4*)(d_V + kbase + (size_t)(pr + j * 16) * 512 + pd4);
            }
        }

        // ---- QK^T ----
        float s[2][2][4];
#pragma unroll
        for (int mt = 0; mt < 2; mt++)
#pragma unroll
            for (int nt = 0; nt < 2; nt++)
#pragma unroll
                for (int r = 0; r < 4; r++) s[mt][nt][r] = 0.f;
#pragma unroll
        for (int ks = 0; ks < 8; ks++) {
            int kk = ks * 8;
            uint32_t af[2][4], bf[2][2];
#pragma unroll
            for (int mt = 0; mt < 2; mt++) {
                int row = wm * 32 + mt * 16 + grp;
                af[mt][0] = U(qs[row * PK + kk + t4]);
                af[mt][1] = U(qs[(row + 8) * PK + kk + t4]);
                af[mt][2] = U(qs[row * PK + kk + t4 + 4]);
                af[mt][3] = U(qs[(row + 8) * PK + kk + t4 + 4]);
            }
#pragma unroll
            for (int nt = 0; nt < 2; nt++) {
                int key = wn * 16 + nt * 8 + grp;
                bf[nt][0] = U(Ks[key * PK + kk + t4]);
                bf[nt][1] = U(Ks[key * PK + kk + t4 + 4]);
            }
#pragma unroll
            for (int mt = 0; mt < 2; mt++)
#pragma unroll
                for (int nt = 0; nt < 2; nt++)
                    mma_tf32(s[mt][nt], af[mt], bf[nt]);
        }

        // mask + scale
#pragma unroll
        for (int mt = 0; mt < 2; mt++)
#pragma unroll
            for (int nt = 0; nt < 2; nt++)
#pragma unroll
                for (int r = 0; r < 4; r++) {
                    int qp = qbase + wm * 32 + mt * 16 + grp + (r >> 1) * 8;
                    int kp = kb * 64 + wn * 16 + nt * 8 + 2 * t4 + (r & 1);
                    bool valid = (kp <= qp) && (!winph || (kp + 512 > qp));
                    s[mt][nt][r] = valid ? s[mt][nt][r] * 0.125f : -1e30f;
                }

#pragma unroll
        for (int mt = 0; mt < 2; mt++)
#pragma unroll
            for (int hf = 0; hf < 2; hf++) {
                float rm = fmaxf(fmaxf(s[mt][0][2 * hf], s[mt][0][2 * hf + 1]),
                                 fmaxf(s[mt][1][2 * hf], s[mt][1][2 * hf + 1]));
                rm = fmaxf(rm, __shfl_xor_sync(0xffffffffu, rm, 1));
                rm = fmaxf(rm, __shfl_xor_sync(0xffffffffu, rm, 2));
                if (t4 == 0)
                    redm[(wm * 32 + mt * 16 + grp + hf * 8) * 4 + wn] = rm;
            }
        __syncthreads();

        float corr[2][2], mnew[2][2];
#pragma unroll
        for (int mt = 0; mt < 2; mt++)
#pragma unroll
            for (int hf = 0; hf < 2; hf++) {
                int row = wm * 32 + mt * 16 + grp + hf * 8;
                float gmax = fmaxf(fmaxf(redm[row * 4 + 0], redm[row * 4 + 1]),
                                   fmaxf(redm[row * 4 + 2], redm[row * 4 + 3]));
                float mn = fmaxf(mst[mt][hf], gmax);
                mnew[mt][hf] = mn;
                corr[mt][hf] = __expf(mst[mt][hf] - mn);
            }

#pragma unroll
        for (int mt = 0; mt < 2; mt++)
#pragma unroll
            for (int hf = 0; hf < 2; hf++) {
                int rowl = wm * 32 + mt * 16 + grp + hf * 8;
                float mn = mnew[mt][hf];
                float rs = 0.f;
#pragma unroll
                for (int nt = 0; nt < 2; nt++) {
                    float p0 = __expf(s[mt][nt][2 * hf]     - mn);
                    float p1 = __expf(s[mt][nt][2 * hf + 1] - mn);
                    rs += p0 + p1;
                    int col = wn * 16 + nt * 8 + 2 * t4;
                    ps[rowl * PK + col]     = ftf(p0);
                    ps[rowl * PK + col + 1] = ftf(p1);
                }
                rs += __shfl_xor_sync(0xffffffffu, rs, 1);
                rs += __shfl_xor_sync(0xffffffffu, rs, 2);
                if (t4 == 0) reds[rowl * 4 + wn] = rs;
            }
        __syncthreads();

#pragma unroll
        for (int mt = 0; mt < 2; mt++)
#pragma unroll
            for (int hf = 0; hf < 2; hf++) {
                int row = wm * 32 + mt * 16 + grp + hf * 8;
                float ls = reds[row * 4 + 0] + reds[row * 4 + 1] +
                           reds[row * 4 + 2] + reds[row * 4 + 3];
                float cr = corr[mt][hf];
                lst[mt][hf] = lst[mt][hf] * cr + ls;
                mst[mt][hf] = mnew[mt][hf];
#pragma unroll
                for (int nt = 0; nt < 2; nt++) {
                    o[mt][nt][2 * hf]     *= cr;
                    o[mt][nt][2 * hf + 1] *= cr;
                }
            }

        // ---- P*V ----
#pragma unroll
        for (int ks = 0; ks < 8; ks++) {
            int kk = ks * 8;
            uint32_t af[2][4], bf[2][2];
#pragma unroll
            for (int mt = 0; mt < 2; mt++) {
                int row = wm * 32 + mt * 16 + grp;
                af[mt][0] = U(ps[row * PK + kk + t4]);
                af[mt][1] = U(ps[(row + 8) * PK + kk + t4]);
                af[mt][2] = U(ps[row * PK + kk + t4 + 4]);
                af[mt][3] = U(ps[(row + 8) * PK + kk + t4 + 4]);
            }
#pragma unroll
            for (int nt = 0; nt < 2; nt++) {
                int dcol = wn * 16 + nt * 8 + grp;
                bf[nt][0] = U(Vs[(kk + t4) * PV + dcol]);
                bf[nt][1] = U(Vs[(kk + t4 + 4) * PV + dcol]);
            }
#pragma unroll
            for (int mt = 0; mt < 2; mt++)
#pragma unroll
                for (int nt = 0; nt < 2; nt++)
                    mma_tf32(o[mt][nt], af[mt], bf[nt]);
        }
        __syncthreads();
    }

    // finalize win phase + single combined RMW
#pragma unroll
    for (int mt = 0; mt < 2; mt++)
#pragma unroll
        for (int hf = 0; hf < 2; hf++) {
            int qp = qbase + wm * 32 + mt * 16 + grp + hf * 8;
            float inv = gv2[mt][hf] / lst[mt][hf];
#pragma unroll
            for (int nt = 0; nt < 2; nt++) {
                int dcol = wn * 16 + nt * 8 + 2 * t4;
                size_t ob = (size_t)(b * SEQ + qp) * 512 + hh * 64 + dcol;
                float2 cur = *(float2*)(d_O + ob);
                cur.x += out_acc[mt][nt][2 * hf]     + o[mt][nt][2 * hf]     * inv;
                cur.y += out_acc[mt][nt][2 * hf + 1] + o[mt][nt][2 * hf + 1] * inv;
                *(float2*)(d_O + ob) = cur;
            }
        }
}

// ---------------------------------------------------------------------------
extern "C" void kernel_launch(void* const* d_in, const int* in_sizes, int n_in,
                              void* d_out, int out_size)
{
    const float* x  = (const float*)d_in[0];
    const float* Wq = (const float*)d_in[1];
    const float* Wk = (const float*)d_in[2];
    const float* Wv = (const float*)d_in[3];
    const float* Wo = (const float*)d_in[4];
    const float* Wg = (const float*)d_in[5];
    float* y = (float*)d_out;

    cudaFuncSetAttribute(cmp_attn_mma,
                         cudaFuncAttributeMaxDynamicSharedMemorySize, 90368);
    cudaFuncSetAttribute(selwin_fused,
                         cudaFuncAttributeMaxDynamicSharedMemorySize, 72704);

    gemm512_tc<<<dim3(8, 64, 3), 256>>>(x, Wq, Wk, Wv, nullptr, 0);
    gate_kernel<<<NROWS, 128>>>(x, Wg);
    compress_kernel<<<(BATCH * NH * NC * HD) / 256, 256>>>();
    cmp_attn_mma<<<dim3(64, 8, 2), 256, 90368>>>();
    selwin_fused<<<dim3(64, 8, 2), 256, 72704>>>();
    gemm512_tc<<<dim3(8, 64, 1), 256>>>(nullptr, Wo, nullptr, nullptr, y, 3);
}

// round 7
// speedup vs baseline: 6.3272x; 1.0774x over previous
#include <cuda_runtime.h>
#include <math.h>
#include <stdint.h>

#define BATCH   2
#define SEQ     4096
#define DMODEL  512
#define NH      8
#define HD      64
#define NC      128
#define NS      64
#define TOPK    16
#define NROWS   (BATCH*SEQ)

// ---------------- scratch ----------------
__device__ float d_Q[NROWS*DMODEL];
__device__ float d_K[NROWS*DMODEL];
__device__ float d_V[NROWS*DMODEL];
__device__ float d_O[NROWS*DMODEL];
__device__ float d_KC[BATCH*NH*NC*HD];
__device__ float d_VC[BATCH*NH*NC*HD];
__device__ float d_G[NROWS*3];
__device__ int   d_SEL[BATCH*NH*NS*TOPK];

// ---------------- tf32 helpers ----------------
__device__ __forceinline__ float ftf(float x) {
    uint32_t u;
    asm("cvt.rna.tf32.f32 %0, %1;" : "=r"(u) : "f"(x));
    return __uint_as_float(u);
}
__device__ __forceinline__ float4 ftf4(float4 v) {
    return make_float4(ftf(v.x), ftf(v.y), ftf(v.z), ftf(v.w));
}
__device__ __forceinline__ void mma_tf32(float* c, const uint32_t* a, const uint32_t* b) {
    asm volatile(
        "mma.sync.aligned.m16n8k8.row.col.f32.tf32.tf32.f32 "
        "{%0,%1,%2,%3},{%4,%5,%6,%7},{%8,%9},{%0,%1,%2,%3};\n"
        : "+f"(c[0]), "+f"(c[1]), "+f"(c[2]), "+f"(c[3])
        : "r"(a[0]), "r"(a[1]), "r"(a[2]), "r"(a[3]), "r"(b[0]), "r"(b[1]));
}
__device__ __forceinline__ void split_tf32(float x, uint32_t& hi, uint32_t& lo) {
    float h = ftf(x);
    hi = __float_as_uint(h);
    lo = __float_as_uint(ftf(x - h));
}
#define U(x) __float_as_uint(x)

// ---------------- tf32 GEMM: 128x128 block tile, reg prefetch -------------
#define GPA 20
#define GPB 136
__global__ __launch_bounds__(256) void gemm512_tc(const float* __restrict__ Aext,
    const float* __restrict__ B0, const float* __restrict__ B1,
    const float* __restrict__ B2, float* __restrict__ Cext, int modeBase)
{
    int mode = modeBase + blockIdx.z;
    const float* A  = (mode == 3) ? d_O : Aext;
    const float* Bm = (mode == 1) ? B1 : (mode == 2) ? B2 : B0;
    float* C = (mode == 0) ? d_Q : (mode == 1) ? d_K : (mode == 2) ? d_V : Cext;

    __shared__ float As[128 * GPA];
    __shared__ float Bs[16 * GPB];

    int tid = threadIdx.x, lane = tid & 31, w = tid >> 5;
    int grp = lane >> 2, t4 = lane & 3;
    int wm = w & 3, wn = w >> 2;
    int m0 = blockIdx.y * 128, n0 = blockIdx.x * 128;

    // A: 512 float4 (128r x 4), B: 512 float4 (16r x 32)
    int ar0 = tid >> 2,           ak0 = (tid & 3) * 4;
    int ar1 = (tid + 256) >> 2,   ak1 = ((tid + 256) & 3) * 4;
    int br0 = tid >> 5,           bc0 = (tid & 31) * 4;
    int br1 = (tid + 256) >> 5,   bc1 = ((tid + 256) & 31) * 4;

    float acc[2][8][4];
#pragma unroll
    for (int mt = 0; mt < 2; mt++)
#pragma unroll
        for (int nt = 0; nt < 8; nt++)
#pragma unroll
            for (int r = 0; r < 4; r++) acc[mt][nt][r] = 0.f;

    float4 apre0 = *(const float4*)(A + (size_t)(m0 + ar0) * 512 + ak0);
    float4 apre1 = *(const float4*)(A + (size_t)(m0 + ar1) * 512 + ak1);
    float4 bpre0 = *(const float4*)(Bm + (size_t)br0 * 512 + n0 + bc0);
    float4 bpre1 = *(const float4*)(Bm + (size_t)br1 * 512 + n0 + bc1);

    for (int k0 = 0; k0 < 512; k0 += 16) {
        *(float4*)(&As[ar0 * GPA + ak0]) = ftf4(apre0);
        *(float4*)(&As[ar1 * GPA + ak1]) = ftf4(apre1);
        *(float4*)(&Bs[br0 * GPB + bc0]) = ftf4(bpre0);
        *(float4*)(&Bs[br1 * GPB + bc1]) = ftf4(bpre1);
        __syncthreads();
        if (k0 + 16 < 512) {
            apre0 = *(const float4*)(A + (size_t)(m0 + ar0) * 512 + k0 + 16 + ak0);
            apre1 = *(const float4*)(A + (size_t)(m0 + ar1) * 512 + k0 + 16 + ak1);
            bpre0 = *(const float4*)(Bm + (size_t)(k0 + 16 + br0) * 512 + n0 + bc0);
            bpre1 = *(const float4*)(Bm + (size_t)(k0 + 16 + br1) * 512 + n0 + bc1);
        }
#pragma unroll
        for (int ks = 0; ks < 2; ks++) {
            int kb = ks * 8;
            uint32_t af[2][4], bf[8][2];
#pragma unroll
            for (int mt = 0; mt < 2; mt++) {
                int row = wm * 32 + mt * 16 + grp;
                af[mt][0] = U(As[row * GPA + kb + t4]);
                af[mt][1] = U(As[(row + 8) * GPA + kb + t4]);
                af[mt][2] = U(As[row * GPA + kb + t4 + 4]);
                af[mt][3] = U(As[(row + 8) * GPA + kb + t4 + 4]);
            }
#pragma unroll
            for (int nt = 0; nt < 8; nt++) {
                int col = wn * 64 + nt * 8 + grp;
                bf[nt][0] = U(Bs[(kb + t4) * GPB + col]);
                bf[nt][1] = U(Bs[(kb + t4 + 4) * GPB + col]);
            }
#pragma unroll
            for (int mt = 0; mt < 2; mt++)
#pragma unroll
                for (int nt = 0; nt < 8; nt++)
                    mma_tf32(acc[mt][nt], af[mt], bf[nt]);
        }
        __syncthreads();
    }
#pragma unroll
    for (int mt = 0; mt < 2; mt++)
#pragma unroll
        for (int nt = 0; nt < 8; nt++) {
            int row = m0 + wm * 32 + mt * 16 + grp;
            int col = n0 + wn * 64 + nt * 8 + 2 * t4;
            *(float2*)(C + (size_t)row * 512 + col) =
                make_float2(acc[mt][nt][0], acc[mt][nt][1]);
            *(float2*)(C + (size_t)(row + 8) * 512 + col) =
                make_float2(acc[mt][nt][2], acc[mt][nt][3]);
        }
}

// ---------------- gate: warp per row, float4 loads ----------------
__global__ __launch_bounds__(256) void gate_kernel(const float* __restrict__ x,
                                                   const float* __restrict__ Wg)
{
    int w = threadIdx.x >> 5, lane = threadIdx.x & 31;
    int row = blockIdx.x * 8 + w;
    float p0 = 0, p1 = 0, p2 = 0;
#pragma unroll
    for (int c = 0; c < 4; c++) {
        int d = c * 128 + lane * 4;
        float4 xv = *(const float4*)(x + (size_t)row * 512 + d);
        p0 += xv.x * Wg[d * 3]     + xv.y * Wg[d * 3 + 3] +
              xv.z * Wg[d * 3 + 6] + xv.w * Wg[d * 3 + 9];
        p1 += xv.x * Wg[d * 3 + 1] + xv.y * Wg[d * 3 + 4] +
              xv.z * Wg[d * 3 + 7] + xv.w * Wg[d * 3 + 10];
        p2 += xv.x * Wg[d * 3 + 2] + xv.y * Wg[d * 3 + 5] +
              xv.z * Wg[d * 3 + 8] + xv.w * Wg[d * 3 + 11];
    }
#pragma unroll
    for (int o = 16; o; o >>= 1) {
        p0 += __shfl_xor_sync(0xffffffffu, p0, o);
        p1 += __shfl_xor_sync(0xffffffffu, p1, o);
        p2 += __shfl_xor_sync(0xffffffffu, p2, o);
    }
    if (lane == 0) {
        d_G[row * 3 + 0] = 1.f / (1.f + expf(-p0));
        d_G[row * 3 + 1] = 1.f / (1.f + expf(-p1));
        d_G[row * 3 + 2] = 1.f / (1.f + expf(-p2));
    }
}

// ---------------- compressed K/V means ----------------
__global__ __launch_bounds__(256) void compress_kernel()
{
    int idx = blockIdx.x * 256 + threadIdx.x;
    int d = idx & 63, n = (idx >> 6) & 127, h = (idx >> 13) & 7, b = idx >> 16;
    const float* kp = d_K + (size_t)(b * SEQ + n * 32) * 512 + h * 64 + d;
    const float* vp = d_V + (size_t)(b * SEQ + n * 32) * 512 + h * 64 + d;
    float ks = 0, vs = 0;
#pragma unroll
    for (int r = 0; r < 32; r++) { ks += kp[r * 512]; vs += vp[r * 512]; }
    d_KC[idx] = ks * (1.f / 32.f);
    d_VC[idx] = vs * (1.f / 32.f);
}

// ---------------- compressed attention + top-k (3xTF32 QK) ----------------
#define CQ 68
#define CK 72
#define CS 132
__global__ __launch_bounds__(256) void cmp_attn_mma()
{
    extern __shared__ float sm[];
    float* qs   = sm;                  // 64*68  (raw fp32 Q)
    float* kv   = qs + 64 * CQ;        // 128*72 (raw fp32 Kc, then Vc)
    float* ps   = kv + 128 * CK;       // 64*132 (probs, fp32)
    float* redm = ps + 64 * CS;        // 64*4
    float* reds = redm + 256;          // 64*4
    float* impb = reds + 256;          // 64

    int g = blockIdx.x, h = blockIdx.y, b = blockIdx.z;
    int tid = threadIdx.x, lane = tid & 31, w = tid >> 5;
    int grp = lane >> 2, t4 = lane & 3;
    int wm = w & 1, wn = w >> 1;
    int qbase = g * 64;

    for (int i = tid; i < 1024; i += 256) {
        int r = i >> 4, d4 = (i & 15) * 4;
        float4 v = *(const float4*)(d_Q + (size_t)(b * SEQ + qbase + r) * 512 + h * 64 + d4);
        *(float4*)(&qs[r * CQ + d4]) = v;
    }
    int cbase = ((b * NH + h) * NC) * HD;
    for (int i = tid; i < 2048; i += 256) {
        int r = i >> 4, d4 = (i & 15) * 4;
        float4 v = *(const float4*)(d_KC + cbase + r * 64 + d4);
        *(float4*)(&kv[r * CK + d4]) = v;
    }
    __syncthreads();

    float s[2][4][4];
#pragma unroll
    for (int mt = 0; mt < 2; mt++)
#pragma unroll
        for (int nt = 0; nt < 4; nt++)
#pragma unroll
            for (int r = 0; r < 4; r++) s[mt][nt][r] = 0.f;
#pragma unroll
    for (int ks = 0; ks < 8; ks++) {
        int kk = ks * 8;
        uint32_t ah[2][4], al[2][4], bh[4][2], bl[4][2];
#pragma unroll
        for (int mt = 0; mt < 2; mt++) {
            int row = wm * 32 + mt * 16 + grp;
            split_tf32(qs[row * CQ + kk + t4],           ah[mt][0], al[mt][0]);
            split_tf32(qs[(row + 8) * CQ + kk + t4],     ah[mt][1], al[mt][1]);
            split_tf32(qs[row * CQ + kk + t4 + 4],       ah[mt][2], al[mt][2]);
            split_tf32(qs[(row + 8) * CQ + kk + t4 + 4], ah[mt][3], al[mt][3]);
        }
#pragma unroll
        for (int nt = 0; nt < 4; nt++) {
            int key = wn * 32 + nt * 8 + grp;
            split_tf32(kv[key * CK + kk + t4],     bh[nt][0], bl[nt][0]);
            split_tf32(kv[key * CK + kk + t4 + 4], bh[nt][1], bl[nt][1]);
        }
#pragma unroll
        for (int mt = 0; mt < 2; mt++)
#pragma unroll
            for (int nt = 0; nt < 4; nt++) {
                mma_tf32(s[mt][nt], ah[mt], bl[nt]);
                mma_tf32(s[mt][nt], al[mt], bh[nt]);
                mma_tf32(s[mt][nt], ah[mt], bh[nt]);
            }
    }

    int nval[2][2];
#pragma unroll
    for (int mt = 0; mt < 2; mt++)
#pragma unroll
        for (int hf = 0; hf < 2; hf++) {
            int pos = qbase + wm * 32 + mt * 16 + grp + hf * 8;
            nval[mt][hf] = (pos >= 31) ? ((pos - 31) >> 5) + 1 : 0;
        }
#pragma unroll
    for (int mt = 0; mt < 2; mt++)
#pragma unroll
        for (int nt = 0; nt < 4; nt++)
#pragma unroll
            for (int r = 0; r < 4; r++) {
                int c = wn * 32 + nt * 8 + 2 * t4 + (r & 1);
                bool valid = c < nval[mt][r >> 1];
                s[mt][nt][r] = valid ? s[mt][nt][r] * 0.125f : -1e30f;
            }

#pragma unroll
    for (int mt = 0; mt < 2; mt++)
#pragma unroll
        for (int hf = 0; hf < 2; hf++) {
            float rm = -1e30f;
#pragma unroll
            for (int nt = 0; nt < 4; nt++)
                rm = fmaxf(rm, fmaxf(s[mt][nt][2 * hf], s[mt][nt][2 * hf + 1]));
            rm = fmaxf(rm, __shfl_xor_sync(0xffffffffu, rm, 1));
            rm = fmaxf(rm, __shfl_xor_sync(0xffffffffu, rm, 2));
            if (t4 == 0)
                redm[(wm * 32 + mt * 16 + grp + hf * 8) * 4 + wn] = rm;
        }
    __syncthreads();

    for (int i = tid; i < 2048; i += 256) {
        int r = i >> 4, d4 = (i & 15) * 4;
        float4 v = *(const float4*)(d_VC + cbase + r * 64 + d4);
        *(float4*)(&kv[r * CK + d4]) = v;
    }
#pragma unroll
    for (int mt = 0; mt < 2; mt++)
#pragma unroll
        for (int hf = 0; hf < 2; hf++) {
            int row = wm * 32 + mt * 16 + grp + hf * 8;
            float4 rmv = *(float4*)(&redm[row * 4]);
            float gmax = fmaxf(fmaxf(rmv.x, rmv.y), fmaxf(rmv.z, rmv.w));
            float rs = 0.f;
#pragma unroll
            for (int nt = 0; nt < 4; nt++) {
                float e0 = __expf(s[mt][nt][2 * hf]     - gmax);
                float e1 = __expf(s[mt][nt][2 * hf + 1] - gmax);
                s[mt][nt][2 * hf] = e0;
                s[mt][nt][2 * hf + 1] = e1;
                rs += e0 + e1;
            }
            rs += __shfl_xor_sync(0xffffffffu, rs, 1);
            rs += __shfl_xor_sync(0xffffffffu, rs, 2);
            if (t4 == 0) reds[row * 4 + wn] = rs;
        }
    __syncthreads();

#pragma unroll
    for (int mt = 0; mt < 2; mt++)
#pragma unroll
        for (int hf = 0; hf < 2; hf++) {
            int row = wm * 32 + mt * 16 + grp + hf * 8;
            float4 rsv = *(float4*)(&reds[row * 4]);
            float tot = rsv.x + rsv.y + rsv.z + rsv.w;
            float inv = (nval[mt][hf] > 0) ? 1.f / tot : 0.f;
#pragma unroll
            for (int nt = 0; nt < 4; nt++) {
                int col = wn * 32 + nt * 8 + 2 * t4;
                ps[row * CS + col]     = s[mt][nt][2 * hf]     * inv;
                ps[row * CS + col + 1] = s[mt][nt][2 * hf + 1] * inv;
            }
        }
    __syncthreads();

    float o[2][2][4];
#pragma unroll
    for (int mt = 0; mt < 2; mt++)
#pragma unroll
        for (int nt = 0; nt < 2; nt++)
#pragma unroll
            for (int r = 0; r < 4; r++) o[mt][nt][r] = 0.f;
#pragma unroll
    for (int ks = 0; ks < 16; ks++) {
        int kk = ks * 8;
        uint32_t af[2][4], bf[2][2];
#pragma unroll
        for (int mt = 0; mt < 2; mt++) {
            int row = wm * 32 + mt * 16 + grp;
            af[mt][0] = U(ftf(ps[row * CS + kk + t4]));
            af[mt][1] = U(ftf(ps[(row + 8) * CS + kk + t4]));
            af[mt][2] = U(ftf(ps[row * CS + kk + t4 + 4]));
            af[mt][3] = U(ftf(ps[(row + 8) * CS + kk + t4 + 4]));
        }
#pragma unroll
        for (int nt = 0; nt < 2; nt++) {
            int dcol = wn * 16 + nt * 8 + grp;
            bf[nt][0] = U(ftf(kv[(kk + t4) * CK + dcol]));
            bf[nt][1] = U(ftf(kv[(kk + t4 + 4) * CK + dcol]));
        }
#pragma unroll
        for (int mt = 0; mt < 2; mt++)
#pragma unroll
            for (int nt = 0; nt < 2; nt++)
                mma_tf32(o[mt][nt], af[mt], bf[nt]);
    }

#pragma unroll
    for (int mt = 0; mt < 2; mt++)
#pragma unroll
        for (int hf = 0; hf < 2; hf++) {
            int qp = qbase + wm * 32 + mt * 16 + grp + hf * 8;
            float g0 = d_G[(b * SEQ + qp) * 3 + 0];
#pragma unroll
            for (int nt = 0; nt < 2; nt++) {
                int dcol = wn * 16 + nt * 8 + 2 * t4;
                size_t ob = (size_t)(b * SEQ + qp) * 512 + h * 64 + dcol;
                *(float2*)(d_O + ob) = make_float2(o[mt][nt][2 * hf] * g0,
                                                   o[mt][nt][2 * hf + 1] * g0);
            }
        }
    __syncthreads();

    if (tid < 64) {
        float v = 0.f;
        for (int q = 0; q < 64; q++)
            v += ps[q * CS + 2 * tid] + ps[q * CS + 2 * tid + 1];
        impb[tid] = v;
    }
    __syncthreads();
    if (w == 0) {
        int j0 = lane, j1 = lane + 32;
        float v0 = (j0 <= g) ? impb[j0] + (j0 == g ? 1e9f : 0.f) : -1e30f;
        float v1 = (j1 <= g) ? impb[j1] + (j1 == g ? 1e9f : 0.f) : -1e30f;
        int selbase = ((b * NH + h) * NS + g) * TOPK;
        for (int r = 0; r < TOPK; r++) {
            float bv; int bi;
            if (v0 >= v1) { bv = v0; bi = j0; } else { bv = v1; bi = j1; }
#pragma unroll
            for (int o2 = 16; o2; o2 >>= 1) {
                float ov = __shfl_xor_sync(0xffffffffu, bv, o2);
                int   oi = __shfl_xor_sync(0xffffffffu, bi, o2);
                if (ov > bv || (ov == bv && oi < bi)) { bv = ov; bi = oi; }
            }
            if (lane == 0) d_SEL[selbase + r] = bi;
            if (bi == j0) v0 = -3e30f;
            if (bi == j1) v1 = -3e30f;
        }
    }
}

// ---------------- fused sel+win flash attention (paired layouts) -----------
// qs, ps stored in paired-k layout: pos(k) = (k&~7) + 2*(k&3) + ((k>>2)&1),
// stride 72 -> A-fragments load as conflict-free LDS.64.
// Ks stride 68 (scalar B-frags), Vs stride 72 (scalar B-frags).
// 3-sync pipeline: K commit after S1 (Ks dead post-QK), V commit after S3.
#define QP 72
#define KP 68
#define VP 72
#define PP 72
__global__ __launch_bounds__(256) void selwin_fused()
{
    extern __shared__ float sm[];
    float* qs   = sm;                 // 64*72 paired
    float* Ks   = qs + 64 * QP;       // 64*68
    float* Vs   = Ks + 64 * KP;       // 64*72
    float* ps   = Vs + 64 * VP;       // 64*72 paired
    float* redm = ps + 64 * PP;       // 64*4
    float* reds = redm + 256;         // 64*4

    int g = blockIdx.x, hh = blockIdx.y, b = blockIdx.z;
    int tid = threadIdx.x, lane = tid & 31, w = tid >> 5;
    int grp = lane >> 2, t4 = lane & 3;
    int wm = w & 1, wn = w >> 1;
    int qbase = g * 64;

    // load Q in paired layout: 512 items (row, 8-group), 2 per thread
#pragma unroll
    for (int ii = 0; ii < 2; ii++) {
        int i = tid + ii * 256;
        int r = i >> 3, g8 = (i & 7) * 8;
        const float* src = d_Q + (size_t)(b * SEQ + qbase + r) * 512 + hh * 64 + g8;
        float4 lo = *(const float4*)src;
        float4 hi = *(const float4*)(src + 4);
        float2* dst = (float2*)(&qs[r * QP + g8]);
        dst[0] = make_float2(ftf(lo.x), ftf(hi.x));
        dst[1] = make_float2(ftf(lo.y), ftf(hi.y));
        dst[2] = make_float2(ftf(lo.z), ftf(hi.z));
        dst[3] = make_float2(ftf(lo.w), ftf(hi.w));
    }

    // combined tile list
    int selbase = ((b * NH + hh) * NS + g) * TOPK;
    int kblist[25];
    int nsel = 0;
#pragma unroll
    for (int it = 0; it < TOPK; it++) {
        int kb = d_SEL[selbase + it];
        if (kb <= g) kblist[nsel++] = kb;
    }
    int ntot = nsel;
    {
        int st = (g > 8) ? g - 8 : 0;
        for (int kb = st; kb <= g; kb++) kblist[ntot++] = kb;
    }

    float gv1[2][2], gv2[2][2];
#pragma unroll
    for (int mt = 0; mt < 2; mt++)
#pragma unroll
        for (int hf = 0; hf < 2; hf++) {
            int qp = qbase + wm * 32 + mt * 16 + grp + hf * 8;
            gv1[mt][hf] = d_G[(b * SEQ + qp) * 3 + 1];
            gv2[mt][hf] = d_G[(b * SEQ + qp) * 3 + 2];
        }

    float out_acc[2][2][4], o[2][2][4];
#pragma unroll
    for (int mt = 0; mt < 2; mt++)
#pragma unroll
        for (int nt = 0; nt < 2; nt++)
#pragma unroll
            for (int r = 0; r < 4; r++) { out_acc[mt][nt][r] = 0.f; o[mt][nt][r] = 0.f; }
    float mst[2][2], lst[2][2];
#pragma unroll
    for (int mt = 0; mt < 2; mt++)
#pragma unroll
        for (int hf = 0; hf < 2; hf++) { mst[mt][hf] = -1e30f; lst[mt][hf] = 0.f; }

    // prefetch: each thread rows pr+16j, cols pd4
    float4 kreg[4], vreg[4];
    int pr = tid >> 4, pd4 = (tid & 15) * 4;
    {
        size_t kbase = (size_t)(b * SEQ + kblist[0] * 64) * 512 + hh * 64;
#pragma unroll
        for (int j = 0; j < 4; j++) {
            kreg[j] = *(const float4*)(d_K + kbase + (size_t)(pr + j * 16) * 512 + pd4);
            vreg[j] = *(const float4*)(d_V + kbase + (size_t)(pr + j * 16) * 512 + pd4);
        }
        // commit tile 0
#pragma unroll
        for (int j = 0; j < 4; j++) {
            int r = pr + j * 16;
            *(float4*)(&Ks[r * KP + pd4]) = ftf4(kreg[j]);
            *(float4*)(&Vs[r * VP + pd4]) = ftf4(vreg[j]);
        }
        // prefetch tile 1
        int nb = (ntot > 1) ? 1 : 0;
        size_t kbase1 = (size_t)(b * SEQ + kblist[nb] * 64) * 512 + hh * 64;
#pragma unroll
        for (int j = 0; j < 4; j++) {
            kreg[j] = *(const float4*)(d_K + kbase1 + (size_t)(pr + j * 16) * 512 + pd4);
            vreg[j] = *(const float4*)(d_V + kbase1 + (size_t)(pr + j * 16) * 512 + pd4);
        }
    }
    __syncthreads();

    // ps write positions (paired): base = wn*16 + nt*8, posA = ((t4&1)<<2)+(t4>>1)
    int posA = ((t4 & 1) << 2) + (t4 >> 1);

    for (int t = 0; t < ntot; t++) {
        if (t == nsel) {
#pragma unroll
            for (int mt = 0; mt < 2; mt++)
#pragma unroll
                for (int hf = 0; hf < 2; hf++) {
                    float inv = gv1[mt][hf] / lst[mt][hf];
#pragma unroll
                    for (int nt = 0; nt < 2; nt++) {
                        out_acc[mt][nt][2 * hf]     += o[mt][nt][2 * hf]     * inv;
                        out_acc[mt][nt][2 * hf + 1] += o[mt][nt][2 * hf + 1] * inv;
                        o[mt][nt][2 * hf] = 0.f; o[mt][nt][2 * hf + 1] = 0.f;
                    }
                    mst[mt][hf] = -1e30f; lst[mt][hf] = 0.f;
                }
        }
        int kb = kblist[t];
        bool winph = (t >= nsel);
        bool more = (t + 1 < ntot);
        int nidx = (t + 2 < ntot) ? t + 2 : ntot - 1;
        size_t nbase = (size_t)(b * SEQ + kblist[nidx] * 64) * 512 + hh * 64;

        // ---- QK^T (qs paired LDS.64, Ks scalar) ----
        float s[2][2][4];
#pragma unroll
        for (int mt = 0; mt < 2; mt++)
#pragma unroll
            for (int nt = 0; nt < 2; nt++)
#pragma unroll
                for (int r = 0; r < 4; r++) s[mt][nt][r] = 0.f;
#pragma unroll
        for (int ks = 0; ks < 8; ks++) {
            int kk = ks * 8;
            uint32_t af[2][4], bf[2][2];
#pragma unroll
            for (int mt = 0; mt < 2; mt++) {
                int row = wm * 32 + mt * 16 + grp;
                float2 a0 = *(float2*)(&qs[row * QP + kk + 2 * t4]);
                float2 a1 = *(float2*)(&qs[(row + 8) * QP + kk + 2 * t4]);
                af[mt][0] = U(a0.x); af[mt][2] = U(a0.y);
                af[mt][1] = U(a1.x); af[mt][3] = U(a1.y);
            }
#pragma unroll
            for (int nt = 0; nt < 2; nt++) {
                int key = wn * 16 + nt * 8 + grp;
                bf[nt][0] = U(Ks[key * KP + kk + t4]);
                bf[nt][1] = U(Ks[key * KP + kk + t4 + 4]);
            }
#pragma unroll
            for (int mt = 0; mt < 2; mt++)
#pragma unroll
                for (int nt = 0; nt < 2; nt++)
                    mma_tf32(s[mt][nt], af[mt], bf[nt]);
        }

        // mask + scale
#pragma unroll
        for (int mt = 0; mt < 2; mt++)
#pragma unroll
            for (int nt = 0; nt < 2; nt++)
#pragma unroll
                for (int r = 0; r < 4; r++) {
                    int qp = qbase + wm * 32 + mt * 16 + grp + (r >> 1) * 8;
                    int kp = kb * 64 + wn * 16 + nt * 8 + 2 * t4 + (r & 1);
                    bool valid = (kp <= qp) && (!winph || (kp + 512 > qp));
                    s[mt][nt][r] = valid ? s[mt][nt][r] * 0.125f : -1e30f;
                }

        // warp row-max partials
#pragma unroll
        for (int mt = 0; mt < 2; mt++)
#pragma unroll
            for (int hf = 0; hf < 2; hf++) {
                float rm = fmaxf(fmaxf(s[mt][0][2 * hf], s[mt][0][2 * hf + 1]),
                                 fmaxf(s[mt][1][2 * hf], s[mt][1][2 * hf + 1]));
                rm = fmaxf(rm, __shfl_xor_sync(0xffffffffu, rm, 1));
                rm = fmaxf(rm, __shfl_xor_sync(0xffffffffu, rm, 2));
                if (t4 == 0)
                    redm[(wm * 32 + mt * 16 + grp + hf * 8) * 4 + wn] = rm;
            }
        __syncthreads();   // S1: QK done (Ks free), redm visible

        // commit next K (overlaps softmax), prefetch K t+2
        if (more) {
#pragma unroll
            for (int j = 0; j < 4; j++)
                *(float4*)(&Ks[(pr + j * 16) * KP + pd4]) = ftf4(kreg[j]);
#pragma unroll
            for (int j = 0; j < 4; j++)
                kreg[j] = *(const float4*)(d_K + nbase + (size_t)(pr + j * 16) * 512 + pd4);
        }

        float corr[2][2], mnew[2][2];
#pragma unroll
        for (int mt = 0; mt < 2; mt++)
#pragma unroll
            for (int hf = 0; hf < 2; hf++) {
                int row = wm * 32 + mt * 16 + grp + hf * 8;
                float4 rmv = *(float4*)(&redm[row * 4]);
                float gmax = fmaxf(fmaxf(rmv.x, rmv.y), fmaxf(rmv.z, rmv.w));
                float mn = fmaxf(mst[mt][hf], gmax);
                mnew[mt][hf] = mn;
                corr[mt][hf] = __expf(mst[mt][hf] - mn);
            }

#pragma unroll
        for (int mt = 0; mt < 2; mt++)
#pragma unroll
            for (int hf = 0; hf < 2; hf++) {
                int rowl = wm * 32 + mt * 16 + grp + hf * 8;
                float mn = mnew[mt][hf];
                float rs = 0.f;
#pragma unroll
                for (int nt = 0; nt < 2; nt++) {
                    float p0 = __expf(s[mt][nt][2 * hf]     - mn);
                    float p1 = __expf(s[mt][nt][2 * hf + 1] - mn);
                    rs += p0 + p1;
                    int gb = wn * 16 + nt * 8;
                    ps[rowl * PP + gb + posA]     = ftf(p0);
                    ps[rowl * PP + gb + posA + 2] = ftf(p1);
                }
                rs += __shfl_xor_sync(0xffffffffu, rs, 1);
                rs += __shfl_xor_sync(0xffffffffu, rs, 2);
                if (t4 == 0) reds[rowl * 4 + wn] = rs;
            }
        __syncthreads();   // S2: ps, reds, next-Ks visible

#pragma unroll
        for (int mt = 0; mt < 2; mt++)
#pragma unroll
            for (int hf = 0; hf < 2; hf++) {
                int row = wm * 32 + mt * 16 + grp + hf * 8;
                float4 rsv = *(float4*)(&reds[row * 4]);
                float ls = rsv.x + rsv.y + rsv.z + rsv.w;
                float cr = corr[mt][hf];
                lst[mt][hf] = lst[mt][hf] * cr + ls;
                mst[mt][hf] = mnew[mt][hf];
#pragma unroll
                for (int nt = 0; nt < 2; nt++) {
                    o[mt][nt][2 * hf]     *= cr;
                    o[mt][nt][2 * hf + 1] *= cr;
                }
            }

        // ---- P*V (ps paired LDS.64, Vs scalar) ----
#pragma unroll
        for (int ks = 0; ks < 8; ks++) {
            int kk = ks * 8;
            uint32_t af[2][4], bf[2][2];
#pragma unroll
            for (int mt = 0; mt < 2; mt++) {
                int row = wm * 32 + mt * 16 + grp;
                float2 p0 = *(float2*)(&ps[row * PP + kk + 2 * t4]);
                float2 p1 = *(float2*)(&ps[(row + 8) * PP + kk + 2 * t4]);
                af[mt][0] = U(p0.x); af[mt][2] = U(p0.y);
                af[mt][1] = U(p1.x); af[mt][3] = U(p1.y);
            }
#pragma unroll
            for (int nt = 0; nt < 2; nt++) {
                int dcol = wn * 16 + nt * 8 + grp;
                bf[nt][0] = U(Vs[(kk + t4) * VP + dcol]);
                bf[nt][1] = U(Vs[(kk + t4 + 4) * VP + dcol]);
            }
#pragma unroll
            for (int mt = 0; mt < 2; mt++)
#pragma unroll
                for (int nt = 0; nt < 2; nt++)
                    mma_tf32(o[mt][nt], af[mt], bf[nt]);
        }
        __syncthreads();   // S3: Vs, ps free

        // commit next V, prefetch V t+2
        if (more) {
#pragma unroll
            for (int j = 0; j < 4; j++)
                *(float4*)(&Vs[(pr + j * 16) * VP + pd4]) = ftf4(vreg[j]);
#pragma unroll
            for (int j = 0; j < 4; j++)
                vreg[j] = *(const float4*)(d_V + nbase + (size_t)(pr + j * 16) * 512 + pd4);
        }
    }

    // finalize win phase + single combined RMW
#pragma unroll
    for (int mt = 0; mt < 2; mt++)
#pragma unroll
        for (int hf = 0; hf < 2; hf++) {
            int qp = qbase + wm * 32 + mt * 16 + grp + hf * 8;
            float inv = gv2[mt][hf] / lst[mt][hf];
#pragma unroll
            for (int nt = 0; nt < 2; nt++) {
                int dcol = wn * 16 + nt * 8 + 2 * t4;
                size_t ob = (size_t)(b * SEQ + qp) * 512 + hh * 64 + dcol;
                float2 cur = *(float2*)(d_O + ob);
                cur.x += out_acc[mt][nt][2 * hf]     + o[mt][nt][2 * hf]     * inv;
                cur.y += out_acc[mt][nt][2 * hf + 1] + o[mt][nt][2 * hf + 1] * inv;
                *(float2*)(d_O + ob) = cur;
            }
        }
}

// ---------------------------------------------------------------------------
extern "C" void kernel_launch(void* const* d_in, const int* in_sizes, int n_in,
                              void* d_out, int out_size)
{
    const float* x  = (const float*)d_in[0];
    const float* Wq = (const float*)d_in[1];
    const float* Wk = (const float*)d_in[2];
    const float* Wv = (const float*)d_in[3];
    const float* Wo = (const float*)d_in[4];
    const float* Wg = (const float*)d_in[5];
    float* y = (float*)d_out;

    cudaFuncSetAttribute(cmp_attn_mma,
                         cudaFuncAttributeMaxDynamicSharedMemorySize, 90368);
    cudaFuncSetAttribute(selwin_fused,
                         cudaFuncAttributeMaxDynamicSharedMemorySize, 74752);

    gemm512_tc<<<dim3(4, 64, 3), 256>>>(x, Wq, Wk, Wv, nullptr, 0);
    gate_kernel<<<NROWS / 8, 256>>>(x, Wg);
    compress_kernel<<<(BATCH * NH * NC * HD) / 256, 256>>>();
    cmp_attn_mma<<<dim3(64, 8, 2), 256, 90368>>>();
    selwin_fused<<<dim3(64, 8, 2), 256, 74752>>>();
    gemm512_tc<<<dim3(4, 64, 1), 256>>>(nullptr, Wo, nullptr, nullptr, y, 3);
}